// round 5
// baseline (speedup 1.0000x reference)
#include <cuda_runtime.h>
#include <cuda_fp16.h>
#include <mma.h>
#include <math.h>

using namespace nvcuda;

#define BATCH   4
#define SEQ     1024
#define DMODEL  256
#define NHEAD   8
#define DHEAD   32
#define DFF     1024
#define NLAYER  6
#define TOK     (BATCH*SEQ)
#define TD      (TOK*DMODEL)          // 1,048,576

// fp32 scratch: X (residual stream)
__device__ __align__(16) float  g_fscratch[TD];
// half scratch: Xh, ENCh, Qh, Kh, Vh, Ch, Hh(4*TD), weights
__device__ __align__(16) __half g_hscratch[16*1024*1024];

#define HOFF_XH  0
#define HOFF_ENC (1*TD)
#define HOFF_Q   (2*TD)
#define HOFF_K   (3*TD)
#define HOFF_V   (4*TD)
#define HOFF_C   (5*TD)
#define HOFF_H   (6*TD)               // TOK*DFF = 4*TD
#define HOFF_W   (10*TD)
#define WSEG     393216               // NL*256*256

// ---------------- cp.async helpers ----------------
__device__ __forceinline__ void cpa16(void* dst, const void* src) {
    unsigned s = (unsigned)__cvta_generic_to_shared(dst);
    asm volatile("cp.async.cg.shared.global [%0], [%1], 16;\n" :: "r"(s), "l"(src));
}
__device__ __forceinline__ void cpa_commit() {
    asm volatile("cp.async.commit_group;\n");
}
template<int N>
__device__ __forceinline__ void cpa_wait() {
    asm volatile("cp.async.wait_group %0;\n" :: "n"(N));
}

// ---------------- batched fp32 -> fp16 convert (one launch) ----------------
struct CvtAll {
    const float* src[11];
    __half*      dst[11];
    int          size[11];
};
__global__ void cvt_all_kernel(CvtAll ca) {
    long idx = ((long)blockIdx.x*blockDim.x + threadIdx.x)*4;
    #pragma unroll
    for (int s = 0; s < 11; s++) {
        if (idx < ca.size[s]) {
            float4 v = *(const float4*)&ca.src[s][idx];
            __half2* o = (__half2*)&ca.dst[s][idx];
            o[0] = __floats2half2_rn(v.x, v.y);
            o[1] = __floats2half2_rn(v.z, v.w);
            return;
        }
        idx -= ca.size[s];
    }
}

// ---------------- positional embedding ----------------
__device__ __forceinline__ float pe_val(int l, int d) {
    int j = d & 127;
    double e = -(2.0*(double)j/256.0) * 9.210340371976184;  // ln(10000)
    float invf = (float)exp(e);
    float arg = (float)l * invf;
    return (d < 128) ? sinf(arg) : cosf(arg);
}

// ---------------- embed (+PE layer 0), dual fp32/fp16 out ----------------
__global__ void embed_kernel(const float* __restrict__ dec,
                             const float* __restrict__ W,
                             const float* __restrict__ b,
                             float* __restrict__ x, __half* __restrict__ xh) {
    int row = blockIdx.x;
    int d   = threadIdx.x;
    const float* in = dec + row*3;
    float acc = b[d] + in[0]*W[d] + in[1]*W[DMODEL+d] + in[2]*W[2*DMODEL+d]
              + pe_val(row & (SEQ-1), d);
    x [row*DMODEL + d] = acc;
    xh[row*DMODEL + d] = __float2half(acc);
}

// ---------------- fp16 wmma GEMM (QKV / W1): 64x64x32, 256 thr ----------
struct GArgs {
    const __half* A[3];
    const __half* W[3];
    const float*  bi[3];
    __half*       O[3];
};

#define AS_H 40
#define BS_H 72
#define GEMM_SMEM ((3*64*AS_H + 3*32*BS_H)*2)   // 29184 B

template<bool RELU>
__global__ __launch_bounds__(256)
void gemm_kernel(GArgs ga, int K, int N, int bnshift) {
    extern __shared__ __align__(16) char dsmc[];
    __half* As = (__half*)dsmc;
    __half* Bs = As + 3*64*AS_H;

    int tid = threadIdx.x;
    int w   = tid >> 5;
    int bx  = blockIdx.x;
    int sel = bx >> bnshift;
    int bn  = bx & ((1 << bnshift) - 1);
    int bm  = blockIdx.y;

    const __half* Abase = ga.A[sel] + (size_t)(bm*64)*K;
    const __half* Wbase = ga.W[sel] + bn*64;
    const float*  bias  = ga.bi[sel];

    int wm = w & 3;
    int wn = w >> 2;

    wmma::fragment<wmma::accumulator,16,16,16,float> c[2];
    wmma::fill_fragment(c[0], 0.0f);
    wmma::fill_fragment(c[1], 0.0f);

    auto stage = [&](int t, int buf) {
        __half* Ab = As + buf*64*AS_H;
        __half* Bb = Bs + buf*32*BS_H;
        const __half* Ag = Abase + t*32;
        {
            int r = tid >> 2, c8 = tid & 3;
            cpa16(&Ab[r*AS_H + c8*8], Ag + (size_t)r*K + c8*8);
        }
        const __half* Wg = Wbase + (size_t)(t*32)*N;
        {
            int r = tid >> 3, c8 = tid & 7;
            cpa16(&Bb[r*BS_H + c8*8], Wg + (size_t)r*N + c8*8);
        }
        cpa_commit();
    };

    int T = K >> 5;
    stage(0, 0);
    if (T > 1) stage(1, 1);

    for (int t = 0; t < T; t++) {
        if (t + 1 < T) cpa_wait<1>(); else cpa_wait<0>();
        __syncthreads();
        if (t + 2 < T) stage(t+2, (t+2)%3);

        int buf = t % 3;
        __half* Ab = As + buf*64*AS_H;
        __half* Bb = Bs + buf*32*BS_H;
        #pragma unroll
        for (int kk = 0; kk < 2; kk++) {
            wmma::fragment<wmma::matrix_a,16,16,16,__half,wmma::row_major> a;
            wmma::load_matrix_sync(a, &Ab[(wm*16)*AS_H + kk*16], AS_H);
            #pragma unroll
            for (int j = 0; j < 2; j++) {
                wmma::fragment<wmma::matrix_b,16,16,16,__half,wmma::row_major> bf;
                wmma::load_matrix_sync(bf, &Bb[(kk*16)*BS_H + wn*32 + j*16], BS_H);
                wmma::mma_sync(c[j], a, bf, c[j]);
            }
        }
    }
    __syncthreads();

    float* Cs = (float*)dsmc;   // 64 x 68 floats
    #pragma unroll
    for (int j = 0; j < 2; j++)
        wmma::store_matrix_sync(&Cs[(wm*16)*68 + wn*32 + j*16], c[j], 68,
                                wmma::mem_row_major);
    __syncthreads();

    #pragma unroll
    for (int i = 0; i < 4; i++) {
        int s = tid + i*256;
        int r = s >> 4, c4 = s & 15;
        int gr = bm*64 + r;
        int gc = bn*64 + c4*4;
        float4 v  = *(float4*)&Cs[r*68 + c4*4];
        float4 bb = *(const float4*)&bias[gc];
        v.x += bb.x; v.y += bb.y; v.z += bb.z; v.w += bb.w;
        if (RELU) {
            v.x = fmaxf(v.x, 0.f); v.y = fmaxf(v.y, 0.f);
            v.z = fmaxf(v.z, 0.f); v.w = fmaxf(v.w, 0.f);
        }
        __half2* op = (__half2*)(ga.O[sel] + (size_t)gr*N + gc);
        op[0] = __floats2half2_rn(v.x, v.y);
        op[1] = __floats2half2_rn(v.z, v.w);
    }
}

// ---------------- fused GEMM + bias + residual + LayerNorm (+PE) -------------
// out = LN(A[M,K] @ W[K,256] + bias + X) ; writes X (f32) and Xh (half) in place.
// Tile 32x256 (full row per CTA), 256 threads, 3-stage cp.async.
#define BS2_H 264
#define GLN_SMEM ((3*32*AS_H + 3*32*BS2_H)*2)    // 58368 B

__global__ __launch_bounds__(256)
void gemmln_kernel(const __half* __restrict__ A, const __half* __restrict__ W,
                   const float* __restrict__ bias,
                   const float* __restrict__ gam, const float* __restrict__ bet,
                   float* __restrict__ X, __half* __restrict__ Xh,
                   int K, int addpe) {
    extern __shared__ __align__(16) char dsmc[];
    __half* As = (__half*)dsmc;            // 3 x 32*AS_H
    __half* Bs = As + 3*32*AS_H;           // 3 x 32*BS2_H

    int tid  = threadIdx.x;
    int w    = tid >> 5;
    int lane = tid & 31;
    int bm   = blockIdx.x;

    const __half* Abase = A + (size_t)(bm*32)*K;

    int wm = w & 1;       // 2 row groups of 16
    int wn = w >> 1;      // 4 col groups of 64

    wmma::fragment<wmma::accumulator,16,16,16,float> c[4];
    #pragma unroll
    for (int j = 0; j < 4; j++) wmma::fill_fragment(c[j], 0.0f);

    auto stage = [&](int t, int buf) {
        __half* Ab = As + buf*32*AS_H;
        __half* Bb = Bs + buf*32*BS2_H;
        if (tid < 128) {
            int r = tid >> 2, c8 = tid & 3;
            cpa16(&Ab[r*AS_H + c8*8], Abase + t*32 + (size_t)r*K + c8*8);
        }
        const __half* Wg = W + (size_t)(t*32)*DMODEL;
        #pragma unroll
        for (int i = 0; i < 4; i++) {
            int s = tid + i*256;
            int r = s >> 5, cc = (s & 31)*8;
            cpa16(&Bb[r*BS2_H + cc], Wg + (size_t)r*DMODEL + cc);
        }
        cpa_commit();
    };

    int T = K >> 5;
    stage(0, 0);
    if (T > 1) stage(1, 1);

    for (int t = 0; t < T; t++) {
        if (t + 1 < T) cpa_wait<1>(); else cpa_wait<0>();
        __syncthreads();
        if (t + 2 < T) stage(t+2, (t+2)%3);

        int buf = t % 3;
        __half* Ab = As + buf*32*AS_H;
        __half* Bb = Bs + buf*32*BS2_H;
        #pragma unroll
        for (int kk = 0; kk < 2; kk++) {
            wmma::fragment<wmma::matrix_a,16,16,16,__half,wmma::row_major> a;
            wmma::load_matrix_sync(a, &Ab[(wm*16)*AS_H + kk*16], AS_H);
            #pragma unroll
            for (int j = 0; j < 4; j++) {
                wmma::fragment<wmma::matrix_b,16,16,16,__half,wmma::row_major> bf;
                wmma::load_matrix_sync(bf, &Bb[(kk*16)*BS2_H + wn*64 + j*16], BS2_H);
                wmma::mma_sync(c[j], a, bf, c[j]);
            }
        }
    }
    __syncthreads();

    float* Cs = (float*)dsmc;    // 32 x 260 floats = 33280 B
    #pragma unroll
    for (int j = 0; j < 4; j++)
        wmma::store_matrix_sync(&Cs[(wm*16)*260 + wn*64 + j*16], c[j], 260,
                                wmma::mem_row_major);
    __syncthreads();

    // LayerNorm: warp w handles rows w*4 .. w*4+3; lane covers 8 cols.
    #pragma unroll
    for (int rr = 0; rr < 4; rr++) {
        int r  = w*4 + rr;
        int gr = bm*32 + r;
        int cbase = lane*8;
        float v[8];
        float4 a0 = *(float4*)&Cs[r*260 + cbase];
        float4 a1 = *(float4*)&Cs[r*260 + cbase + 4];
        float4 b0 = *(const float4*)&bias[cbase];
        float4 b1 = *(const float4*)&bias[cbase + 4];
        float4 r0 = *(const float4*)&X[(size_t)gr*DMODEL + cbase];
        float4 r1 = *(const float4*)&X[(size_t)gr*DMODEL + cbase + 4];
        v[0]=a0.x+b0.x+r0.x; v[1]=a0.y+b0.y+r0.y; v[2]=a0.z+b0.z+r0.z; v[3]=a0.w+b0.w+r0.w;
        v[4]=a1.x+b1.x+r1.x; v[5]=a1.y+b1.y+r1.y; v[6]=a1.z+b1.z+r1.z; v[7]=a1.w+b1.w+r1.w;
        float s1 = 0.f, s2 = 0.f;
        #pragma unroll
        for (int q = 0; q < 8; q++) { s1 += v[q]; s2 += v[q]*v[q]; }
        #pragma unroll
        for (int o = 16; o; o >>= 1) {
            s1 += __shfl_xor_sync(0xffffffffu, s1, o);
            s2 += __shfl_xor_sync(0xffffffffu, s2, o);
        }
        float mean = s1 * (1.0f/DMODEL);
        float var  = s2 * (1.0f/DMODEL) - mean*mean;
        float rstd = rsqrtf(var + 1e-5f);
        float4 g0 = *(const float4*)&gam[cbase];
        float4 g1 = *(const float4*)&gam[cbase + 4];
        float4 e0 = *(const float4*)&bet[cbase];
        float4 e1 = *(const float4*)&bet[cbase + 4];
        float o8[8];
        o8[0]=(v[0]-mean)*rstd*g0.x+e0.x; o8[1]=(v[1]-mean)*rstd*g0.y+e0.y;
        o8[2]=(v[2]-mean)*rstd*g0.z+e0.z; o8[3]=(v[3]-mean)*rstd*g0.w+e0.w;
        o8[4]=(v[4]-mean)*rstd*g1.x+e1.x; o8[5]=(v[5]-mean)*rstd*g1.y+e1.y;
        o8[6]=(v[6]-mean)*rstd*g1.z+e1.z; o8[7]=(v[7]-mean)*rstd*g1.w+e1.w;
        if (addpe) {
            int l = gr & (SEQ-1);
            #pragma unroll
            for (int q = 0; q < 8; q++) o8[q] += pe_val(l, cbase + q);
        }
        *(float4*)&X[(size_t)gr*DMODEL + cbase]     = make_float4(o8[0],o8[1],o8[2],o8[3]);
        *(float4*)&X[(size_t)gr*DMODEL + cbase + 4] = make_float4(o8[4],o8[5],o8[6],o8[7]);
        __half2* hp = (__half2*)&Xh[(size_t)gr*DMODEL + cbase];
        hp[0] = __floats2half2_rn(o8[0], o8[1]);
        hp[1] = __floats2half2_rn(o8[2], o8[3]);
        hp[2] = __floats2half2_rn(o8[4], o8[5]);
        hp[3] = __floats2half2_rn(o8[6], o8[7]);
    }
}

// ---------------- fused attention, fp16 MMAs, no-max softmax ----------------
#define ATTN_SMEM 54016

__global__ __launch_bounds__(256)
void attn_kernel(const __half* __restrict__ Qg, const __half* __restrict__ Kg,
                 const __half* __restrict__ Vg, __half* __restrict__ Og,
                 const int* __restrict__ mask, int Lk, int causal) {
    extern __shared__ __align__(16) char smc[];
    __half* Qs    = (__half*)smc;
    __half* KsB[2] = {(__half*)(smc + 5120),  (__half*)(smc + 10240)};
    __half* VsB[2] = {(__half*)(smc + 15360), (__half*)(smc + 20480)};
    float*  Ss    = (float*)(smc + 25600);
    __half* Ps    = (__half*)(smc + 43008);
    float*  rs4   = (float*)(smc + 52224);
    float*  rowsum= (float*)(smc + 53248);
    int*    smask = (int*)  (smc + 53504);

    int tid = threadIdx.x;
    int w   = tid >> 5;
    int qt  = blockIdx.x, h = blockIdx.y, b = blockIdx.z;
    int q0  = qt*64;

    const __half* Qp = Qg + ((size_t)(b*SEQ + q0))*DMODEL + h*DHEAD;
    {
        int r = tid >> 2, c8 = tid & 3;
        *(float4*)&Qs[r*40 + c8*8] = *(const float4*)&Qp[(size_t)r*DMODEL + c8*8];
    }
    if (tid < 64) rowsum[tid] = 0.f;

    const __half* Kbase = Kg + (size_t)b*Lk*DMODEL + h*DHEAD;
    const __half* Vbase = Vg + (size_t)b*Lk*DMODEL + h*DHEAD;

    auto stage_kv = [&](int kt, int buf) {
        int k0 = kt*64;
        const __half* Kp = Kbase + (size_t)k0*DMODEL;
        const __half* Vp = Vbase + (size_t)k0*DMODEL;
        int r = tid >> 2, c8 = tid & 3;
        cpa16(&KsB[buf][r*40 + c8*8], Kp + (size_t)r*DMODEL + c8*8);
        cpa16(&VsB[buf][r*40 + c8*8], Vp + (size_t)r*DMODEL + c8*8);
        if (tid < 64) smask[buf*64 + tid] = mask[b*Lk + k0 + tid];
        cpa_commit();
    };

    __syncthreads();

    int smi = w & 3;
    int sn0 = (w >> 2) * 2;
    wmma::fragment<wmma::matrix_a,16,16,16,__half,wmma::row_major> qa[2];
    #pragma unroll
    for (int kk = 0; kk < 2; kk++)
        wmma::load_matrix_sync(qa[kk], &Qs[smi*16*40 + kk*16], 40);

    int omi = w & 3, oni = w >> 2;
    wmma::fragment<wmma::accumulator,16,16,16,float> of;
    wmma::fill_fragment(of, 0.0f);

    const float inv_sqrt_dk = 0.17677669529663689f;
    int ktend = causal ? (qt + 1) : (Lk >> 6);

    stage_kv(0, 0);

    for (int kt = 0; kt < ktend; kt++) {
        int buf = kt & 1;
        int k0  = kt*64;
        if (kt + 1 < ktend) {
            stage_kv(kt+1, buf ^ 1);
            cpa_wait<1>();
        } else {
            cpa_wait<0>();
        }
        __syncthreads();

        __half* Ks = KsB[buf];
        __half* Vs = VsB[buf];

        #pragma unroll
        for (int nj = 0; nj < 2; nj++) {
            int n = sn0 + nj;
            wmma::fragment<wmma::accumulator,16,16,16,float> cf;
            wmma::fill_fragment(cf, 0.0f);
            #pragma unroll
            for (int kk = 0; kk < 2; kk++) {
                wmma::fragment<wmma::matrix_b,16,16,16,__half,wmma::col_major> kb;
                wmma::load_matrix_sync(kb, &Ks[n*16*40 + kk*16], 40);
                wmma::mma_sync(cf, qa[kk], kb, cf);
            }
            wmma::store_matrix_sync(&Ss[smi*16*68 + n*16], cf, 68, wmma::mem_row_major);
        }
        __syncthreads();

        {
            int r  = tid >> 2;
            int g4 = tid & 3;
            int qi = q0 + r;
            float part = 0.f;
            #pragma unroll
            for (int cc = 0; cc < 16; cc++) {
                int c  = g4*16 + cc;
                int kj = k0 + c;
                float sc = Ss[r*68 + c] * inv_sqrt_dk;
                bool m = (causal && kj > qi) || (smask[buf*64 + c] != 0);
                float p = m ? 0.0f : __expf(sc);
                Ps[r*72 + c] = __float2half(p);
                part += p;
            }
            rs4[r*4 + g4] = part;
        }
        __syncthreads();
        if (tid < 64)
            rowsum[tid] += rs4[tid*4] + rs4[tid*4+1] + rs4[tid*4+2] + rs4[tid*4+3];

        #pragma unroll
        for (int kk = 0; kk < 4; kk++) {
            wmma::fragment<wmma::matrix_a,16,16,16,__half,wmma::row_major> pa;
            wmma::load_matrix_sync(pa, &Ps[omi*16*72 + kk*16], 72);
            wmma::fragment<wmma::matrix_b,16,16,16,__half,wmma::row_major> vb;
            wmma::load_matrix_sync(vb, &Vs[(kk*16)*40 + oni*16], 40);
            wmma::mma_sync(of, pa, vb, of);
        }
        __syncthreads();
    }

    wmma::store_matrix_sync(&Ss[omi*16*36 + oni*16], of, 36, wmma::mem_row_major);
    __syncthreads();
    {
        int r  = tid >> 2;
        int g4 = tid & 3;
        float rinv = 1.0f / rowsum[r];
        __half* op = Og + ((size_t)(b*SEQ + q0 + r))*DMODEL + h*DHEAD + g4*8;
        #pragma unroll
        for (int cc = 0; cc < 8; cc++)
            op[cc] = __float2half(Ss[r*36 + g4*8 + cc] * rinv);
    }
}

// ---------------- orchestration ----------------
extern "C" void kernel_launch(void* const* d_in, const int* in_sizes, int n_in,
                              void* d_out, int out_size) {
    const float* enc      = (const float*)d_in[0];
    const float* dec      = (const float*)d_in[1];
    const int*   enc_mask = (const int*)  d_in[2];
    const int*   dec_mask = (const int*)  d_in[3];
    const float* W_tgt    = (const float*)d_in[4];
    const float* b_tgt    = (const float*)d_in[5];
    const float* sa_Wq = (const float*)d_in[6];  const float* sa_bq = (const float*)d_in[7];
    const float* sa_Wk = (const float*)d_in[8];  const float* sa_bk = (const float*)d_in[9];
    const float* sa_Wv = (const float*)d_in[10]; const float* sa_bv = (const float*)d_in[11];
    const float* sa_Wo = (const float*)d_in[12]; const float* sa_bo = (const float*)d_in[13];
    const float* sa_g  = (const float*)d_in[14]; const float* sa_b  = (const float*)d_in[15];
    const float* ca_Wq = (const float*)d_in[16]; const float* ca_bq = (const float*)d_in[17];
    const float* ca_Wk = (const float*)d_in[18]; const float* ca_bk = (const float*)d_in[19];
    const float* ca_Wv = (const float*)d_in[20]; const float* ca_bv = (const float*)d_in[21];
    const float* ca_Wo = (const float*)d_in[22]; const float* ca_bo = (const float*)d_in[23];
    const float* ca_g  = (const float*)d_in[24]; const float* ca_b  = (const float*)d_in[25];
    const float* ff_W1 = (const float*)d_in[26]; const float* ff_b1 = (const float*)d_in[27];
    const float* ff_W2 = (const float*)d_in[28]; const float* ff_b2 = (const float*)d_in[29];
    const float* ff_g  = (const float*)d_in[30]; const float* ff_b  = (const float*)d_in[31];

    float* fs = nullptr;
    __half* hs = nullptr;
    cudaGetSymbolAddress((void**)&fs, g_fscratch);
    cudaGetSymbolAddress((void**)&hs, g_hscratch);
    float* X = fs;
    __half* Xh  = hs + HOFF_XH;
    __half* ENCh= hs + HOFF_ENC;
    __half* Qh  = hs + HOFF_Q;
    __half* Kh  = hs + HOFF_K;
    __half* Vh  = hs + HOFF_V;
    __half* Ch  = hs + HOFF_C;
    __half* Hh  = hs + HOFF_H;
    __half* Wh  = hs + HOFF_W;

    __half* hsaWq = Wh + 0*WSEG;
    __half* hsaWk = Wh + 1*WSEG;
    __half* hsaWv = Wh + 2*WSEG;
    __half* hsaWo = Wh + 3*WSEG;
    __half* hcaWq = Wh + 4*WSEG;
    __half* hcaWk = Wh + 5*WSEG;
    __half* hcaWv = Wh + 6*WSEG;
    __half* hcaWo = Wh + 7*WSEG;
    __half* hffW1 = Wh + 8*WSEG;
    __half* hffW2 = hffW1 + NLAYER*DMODEL*DFF;

    cudaFuncSetAttribute(attn_kernel, cudaFuncAttributeMaxDynamicSharedMemorySize, ATTN_SMEM);
    cudaFuncSetAttribute(gemm_kernel<false>, cudaFuncAttributeMaxDynamicSharedMemorySize, GEMM_SMEM);
    cudaFuncSetAttribute(gemm_kernel<true >, cudaFuncAttributeMaxDynamicSharedMemorySize, GEMM_SMEM);
    cudaFuncSetAttribute(gemmln_kernel, cudaFuncAttributeMaxDynamicSharedMemorySize, GLN_SMEM);

    // ---- single batched conversion launch ----
    {
        CvtAll ca;
        const float* srcs[11] = {sa_Wq, sa_Wk, sa_Wv, sa_Wo, ca_Wq, ca_Wk, ca_Wv, ca_Wo,
                                 ff_W1, ff_W2, enc};
        __half* dsts[11] = {hsaWq, hsaWk, hsaWv, hsaWo, hcaWq, hcaWk, hcaWv, hcaWo,
                            hffW1, hffW2, ENCh};
        int nF = NLAYER*DMODEL*DFF;
        int szs[11] = {WSEG,WSEG,WSEG,WSEG,WSEG,WSEG,WSEG,WSEG, nF, nF, TD};
        long total = 0;
        for (int i = 0; i < 11; i++) { ca.src[i]=srcs[i]; ca.dst[i]=dsts[i]; ca.size[i]=szs[i]; total += szs[i]; }
        int nThreads = (int)(total/4);
        cvt_all_kernel<<<(nThreads + 255)/256, 256>>>(ca);
    }

    dim3 blkG(256), blkA(256), blkR(256);
    dim3 g_rows(TOK);
    dim3 g_qkv(12, 64);
    dim3 g_1024(16, 64);
    dim3 g_gln(128);
    dim3 g_attn(SEQ/64, NHEAD, BATCH);

    embed_kernel<<<g_rows, blkR>>>(dec, W_tgt, b_tgt, X, Xh);

    const int WD  = DMODEL*DMODEL;
    const int W1S = DMODEL*DFF;
    const int W2S = DFF*DMODEL;

    for (int i = 0; i < NLAYER; i++) {
        // ---- self attention ----
        {
            GArgs ga;
            ga.A[0]=Xh; ga.A[1]=Xh; ga.A[2]=Xh;
            ga.W[0]=hsaWq+i*WD; ga.W[1]=hsaWk+i*WD; ga.W[2]=hsaWv+i*WD;
            ga.bi[0]=sa_bq+i*DMODEL; ga.bi[1]=sa_bk+i*DMODEL; ga.bi[2]=sa_bv+i*DMODEL;
            ga.O[0]=Qh; ga.O[1]=Kh; ga.O[2]=Vh;
            gemm_kernel<false><<<g_qkv, blkG, GEMM_SMEM>>>(ga, DMODEL, DMODEL, 2);
        }
        attn_kernel<<<g_attn, blkA, ATTN_SMEM>>>(Qh, Kh, Vh, Ch, dec_mask, SEQ, 1);
        gemmln_kernel<<<g_gln, blkG, GLN_SMEM>>>(Ch, hsaWo+i*WD, sa_bo+i*DMODEL,
                                                 sa_g+i*DMODEL, sa_b+i*DMODEL,
                                                 X, Xh, DMODEL, 0);

        // ---- cross attention ----
        {
            GArgs ga;
            ga.A[0]=Xh; ga.A[1]=ENCh; ga.A[2]=ENCh;
            ga.W[0]=hcaWq+i*WD; ga.W[1]=hcaWk+i*WD; ga.W[2]=hcaWv+i*WD;
            ga.bi[0]=ca_bq+i*DMODEL; ga.bi[1]=ca_bk+i*DMODEL; ga.bi[2]=ca_bv+i*DMODEL;
            ga.O[0]=Qh; ga.O[1]=Kh; ga.O[2]=Vh;
            gemm_kernel<false><<<g_qkv, blkG, GEMM_SMEM>>>(ga, DMODEL, DMODEL, 2);
        }
        attn_kernel<<<g_attn, blkA, ATTN_SMEM>>>(Qh, Kh, Vh, Ch, enc_mask, SEQ, 0);
        gemmln_kernel<<<g_gln, blkG, GLN_SMEM>>>(Ch, hcaWo+i*WD, ca_bo+i*DMODEL,
                                                 ca_g+i*DMODEL, ca_b+i*DMODEL,
                                                 X, Xh, DMODEL, 0);

        // ---- FFN ----
        {
            GArgs ga{};
            ga.A[0]=Xh; ga.W[0]=hffW1+i*W1S; ga.bi[0]=ff_b1+i*DFF; ga.O[0]=Hh;
            gemm_kernel<true><<<g_1024, blkG, GEMM_SMEM>>>(ga, DMODEL, DFF, 4);
        }
        gemmln_kernel<<<g_gln, blkG, GLN_SMEM>>>(Hh, hffW2+i*W2S, ff_b2+i*DMODEL,
                                                 ff_g+i*DMODEL, ff_b+i*DMODEL,
                                                 X, Xh, DFF, (i < NLAYER-1) ? 1 : 0);
    }

    cudaMemcpyAsync(d_out, X, (size_t)TD*sizeof(float),
                    cudaMemcpyDeviceToDevice);
}

// round 7
// speedup vs baseline: 1.2642x; 1.2642x over previous
#include <cuda_runtime.h>
#include <cuda_fp16.h>
#include <mma.h>
#include <math.h>

using namespace nvcuda;

#define BATCH   4
#define SEQ     1024
#define DMODEL  256
#define NHEAD   8
#define DHEAD   32
#define DFF     1024
#define NLAYER  6
#define TOK     (BATCH*SEQ)
#define TD      (TOK*DMODEL)          // 1,048,576

// fp32 scratch: X (residual stream), T (pre-LN temp)
__device__ __align__(16) float  g_fscratch[2*TD];
// half scratch: Xh, ENCh, Qh, Kh, Vh, Ch, Hh(4*TD), weights
__device__ __align__(16) __half g_hscratch[16*1024*1024];

#define OFF_X 0
#define OFF_T TD

#define HOFF_XH  0
#define HOFF_ENC (1*TD)
#define HOFF_Q   (2*TD)
#define HOFF_K   (3*TD)
#define HOFF_V   (4*TD)
#define HOFF_C   (5*TD)
#define HOFF_H   (6*TD)
#define HOFF_W   (10*TD)
#define WSEG     393216               // NL*256*256

// ---------------- cp.async helpers ----------------
__device__ __forceinline__ void cpa16(void* dst, const void* src) {
    unsigned s = (unsigned)__cvta_generic_to_shared(dst);
    asm volatile("cp.async.cg.shared.global [%0], [%1], 16;\n" :: "r"(s), "l"(src));
}
__device__ __forceinline__ void cpa_commit() {
    asm volatile("cp.async.commit_group;\n");
}
template<int N>
__device__ __forceinline__ void cpa_wait() {
    asm volatile("cp.async.wait_group %0;\n" :: "n"(N));
}

// ---------------- batched fp32 -> fp16 convert (one launch) ----------------
struct CvtAll {
    const float* src[11];
    __half*      dst[11];
    int          size[11];
};
__global__ void cvt_all_kernel(CvtAll ca) {
    long idx = ((long)blockIdx.x*blockDim.x + threadIdx.x)*4;
    #pragma unroll
    for (int s = 0; s < 11; s++) {
        if (idx < ca.size[s]) {
            float4 v = *(const float4*)&ca.src[s][idx];
            __half2* o = (__half2*)&ca.dst[s][idx];
            o[0] = __floats2half2_rn(v.x, v.y);
            o[1] = __floats2half2_rn(v.z, v.w);
            return;
        }
        idx -= ca.size[s];
    }
}

// ---------------- positional embedding ----------------
__device__ __forceinline__ float pe_val(int l, int d) {
    int j = d & 127;
    double e = -(2.0*(double)j/256.0) * 9.210340371976184;  // ln(10000)
    float invf = (float)exp(e);
    float arg = (float)l * invf;
    return (d < 128) ? sinf(arg) : cosf(arg);
}

// ---------------- embed (+PE layer 0), dual fp32/fp16 out ----------------
__global__ void embed_kernel(const float* __restrict__ dec,
                             const float* __restrict__ W,
                             const float* __restrict__ b,
                             float* __restrict__ x, __half* __restrict__ xh) {
    int row = blockIdx.x;
    int d   = threadIdx.x;
    const float* in = dec + row*3;
    float acc = b[d] + in[0]*W[d] + in[1]*W[DMODEL+d] + in[2]*W[2*DMODEL+d]
              + pe_val(row & (SEQ-1), d);
    x [row*DMODEL + d] = acc;
    xh[row*DMODEL + d] = __float2half(acc);
}

// ---------------- LayerNorm, dual out, optional +PE ----------------
__global__ void ln_kernel(const float* __restrict__ t,
                          const float* __restrict__ g,
                          const float* __restrict__ b,
                          float* __restrict__ out, __half* __restrict__ outh,
                          int addpe) {
    int row = blockIdx.x;
    int d   = threadIdx.x;
    float v = t[row*DMODEL + d];

    __shared__ float red[8];
    __shared__ float stats[2];

    float s = v;
    #pragma unroll
    for (int o = 16; o; o >>= 1) s += __shfl_xor_sync(0xffffffffu, s, o);
    if ((d & 31) == 0) red[d >> 5] = s;
    __syncthreads();
    if (d == 0) {
        float m = 0.f;
        #pragma unroll
        for (int i = 0; i < 8; i++) m += red[i];
        stats[0] = m * (1.0f/DMODEL);
    }
    __syncthreads();
    float mean = stats[0];
    float dv = v - mean;
    float s2 = dv*dv;
    #pragma unroll
    for (int o = 16; o; o >>= 1) s2 += __shfl_xor_sync(0xffffffffu, s2, o);
    if ((d & 31) == 0) red[d >> 5] = s2;
    __syncthreads();
    if (d == 0) {
        float var = 0.f;
        #pragma unroll
        for (int i = 0; i < 8; i++) var += red[i];
        stats[1] = rsqrtf(var * (1.0f/DMODEL) + 1e-5f);
    }
    __syncthreads();
    float o = dv * stats[1] * g[d] + b[d];
    if (addpe) o += pe_val(row & (SEQ-1), d);
    out [row*DMODEL + d] = o;
    outh[row*DMODEL + d] = __float2half(o);
}

// ---------------- fp16 wmma GEMM: 64x64x32, 256 thr, 3-stage ----------
struct GArgs {
    const __half* A[3];
    const __half* W[3];
    const float*  bi[3];
    void*         O[3];
};

#define AS_H 40
#define BS_H 72
#define GEMM_SMEM ((3*64*AS_H + 3*32*BS_H)*2)   // 29184 B

template<bool RELU, bool RES, bool OUTH>
__global__ __launch_bounds__(256)
void gemm_kernel(GArgs ga, const float* __restrict__ Rres,
                 int K, int N, int bnshift) {
    extern __shared__ __align__(16) char dsmc[];
    __half* As = (__half*)dsmc;
    __half* Bs = As + 3*64*AS_H;

    int tid = threadIdx.x;
    int w   = tid >> 5;
    int bx  = blockIdx.x;
    int sel = bx >> bnshift;
    int bn  = bx & ((1 << bnshift) - 1);
    int bm  = blockIdx.y;

    const __half* Abase = ga.A[sel] + (size_t)(bm*64)*K;
    const __half* Wbase = ga.W[sel] + bn*64;
    const float*  bias  = ga.bi[sel];

    int wm = w & 3;
    int wn = w >> 2;

    wmma::fragment<wmma::accumulator,16,16,16,float> c[2];
    wmma::fill_fragment(c[0], 0.0f);
    wmma::fill_fragment(c[1], 0.0f);

    auto stage = [&](int t, int buf) {
        __half* Ab = As + buf*64*AS_H;
        __half* Bb = Bs + buf*32*BS_H;
        const __half* Ag = Abase + t*32;
        {
            int r = tid >> 2, c8 = tid & 3;
            cpa16(&Ab[r*AS_H + c8*8], Ag + (size_t)r*K + c8*8);
        }
        const __half* Wg = Wbase + (size_t)(t*32)*N;
        {
            int r = tid >> 3, c8 = tid & 7;
            cpa16(&Bb[r*BS_H + c8*8], Wg + (size_t)r*N + c8*8);
        }
        cpa_commit();
    };

    int T = K >> 5;
    stage(0, 0);
    if (T > 1) stage(1, 1);

    for (int t = 0; t < T; t++) {
        if (t + 1 < T) cpa_wait<1>(); else cpa_wait<0>();
        __syncthreads();
        if (t + 2 < T) stage(t+2, (t+2)%3);

        int buf = t % 3;
        __half* Ab = As + buf*64*AS_H;
        __half* Bb = Bs + buf*32*BS_H;
        #pragma unroll
        for (int kk = 0; kk < 2; kk++) {
            wmma::fragment<wmma::matrix_a,16,16,16,__half,wmma::row_major> a;
            wmma::load_matrix_sync(a, &Ab[(wm*16)*AS_H + kk*16], AS_H);
            #pragma unroll
            for (int j = 0; j < 2; j++) {
                wmma::fragment<wmma::matrix_b,16,16,16,__half,wmma::row_major> bf;
                wmma::load_matrix_sync(bf, &Bb[(kk*16)*BS_H + wn*32 + j*16], BS_H);
                wmma::mma_sync(c[j], a, bf, c[j]);
            }
        }
    }
    __syncthreads();

    float* Cs = (float*)dsmc;   // 64 x 68 floats
    #pragma unroll
    for (int j = 0; j < 2; j++)
        wmma::store_matrix_sync(&Cs[(wm*16)*68 + wn*32 + j*16], c[j], 68,
                                wmma::mem_row_major);
    __syncthreads();

    #pragma unroll
    for (int i = 0; i < 4; i++) {
        int s = tid + i*256;
        int r = s >> 4, c4 = s & 15;
        int gr = bm*64 + r;
        int gc = bn*64 + c4*4;
        float4 v  = *(float4*)&Cs[r*68 + c4*4];
        float4 bb = *(const float4*)&bias[gc];
        v.x += bb.x; v.y += bb.y; v.z += bb.z; v.w += bb.w;
        if (RES) {
            float4 rr = *(const float4*)&Rres[(size_t)gr*N + gc];
            v.x += rr.x; v.y += rr.y; v.z += rr.z; v.w += rr.w;
        }
        if (RELU) {
            v.x = fmaxf(v.x, 0.f); v.y = fmaxf(v.y, 0.f);
            v.z = fmaxf(v.z, 0.f); v.w = fmaxf(v.w, 0.f);
        }
        if (OUTH) {
            __half2* op = (__half2*)((__half*)ga.O[sel] + (size_t)gr*N + gc);
            op[0] = __floats2half2_rn(v.x, v.y);
            op[1] = __floats2half2_rn(v.z, v.w);
        } else {
            *(float4*)((float*)ga.O[sel] + (size_t)gr*N + gc) = v;
        }
    }
}

// ---------------- fused attention v2: 64q x 128k tiles, vectorized softmax -----
// smem (bytes):
//  Qs   @0      : 64x40 half   = 5120
//  Ks0  @5120   : 128x40 half  = 10240    Ks1 @15360
//  Vs0  @25600  : 10240                   Vs1 @35840
//  Ss   @46080  : 64x140 f32   = 35840
//  Ps   @81920  : 64x136 half  = 17408
//  mask @99328  : 2x128 int    = 1024
#define ATTN_SMEM 100352

__global__ __launch_bounds__(256)
void attn_kernel(const __half* __restrict__ Qg, const __half* __restrict__ Kg,
                 const __half* __restrict__ Vg, __half* __restrict__ Og,
                 const int* __restrict__ mask, int Lk, int causal) {
    extern __shared__ __align__(16) char smc[];
    __half* Qs     = (__half*)smc;
    __half* KsB[2] = {(__half*)(smc + 5120),  (__half*)(smc + 15360)};
    __half* VsB[2] = {(__half*)(smc + 25600), (__half*)(smc + 35840)};
    float*  Ss     = (float*)(smc + 46080);
    __half* Ps     = (__half*)(smc + 81920);
    int*    smask  = (int*)  (smc + 99328);

    int tid = threadIdx.x;
    int w   = tid >> 5;
    int qt  = blockIdx.x, h = blockIdx.y, b = blockIdx.z;
    int q0  = qt*64;

    const __half* Qp = Qg + ((size_t)(b*SEQ + q0))*DMODEL + h*DHEAD;
    {
        int r = tid >> 2, c8 = tid & 3;
        *(float4*)&Qs[r*40 + c8*8] = *(const float4*)&Qp[(size_t)r*DMODEL + c8*8];
    }

    const __half* Kbase = Kg + (size_t)b*Lk*DMODEL + h*DHEAD;
    const __half* Vbase = Vg + (size_t)b*Lk*DMODEL + h*DHEAD;

    auto stage_kv = [&](int it, int buf) {
        int k0 = it*128;
        const __half* Kp = Kbase + (size_t)k0*DMODEL;
        const __half* Vp = Vbase + (size_t)k0*DMODEL;
        #pragma unroll
        for (int i = 0; i < 2; i++) {
            int s = tid + i*256;
            int r = s >> 2, c8 = s & 3;
            cpa16(&KsB[buf][r*40 + c8*8], Kp + (size_t)r*DMODEL + c8*8);
            cpa16(&VsB[buf][r*40 + c8*8], Vp + (size_t)r*DMODEL + c8*8);
        }
        if (tid < 128) smask[buf*128 + tid] = mask[b*Lk + k0 + tid];
        cpa_commit();
    };

    __syncthreads();   // Qs visible

    // persistent Q frags: warp w -> S rows (w&3)*16, S col half (w>>2)*64
    int smi = w & 3;
    int sch = w >> 2;
    wmma::fragment<wmma::matrix_a,16,16,16,__half,wmma::row_major> qa[2];
    #pragma unroll
    for (int kk = 0; kk < 2; kk++)
        wmma::load_matrix_sync(qa[kk], &Qs[smi*16*40 + kk*16], 40);

    // O accumulator: warp w -> O rows (w&3)*16, O cols (w>>2)*16
    wmma::fragment<wmma::accumulator,16,16,16,float> of;
    wmma::fill_fragment(of, 0.0f);

    // softmax thread mapping: row r (owned by quad), 32 interleaved cols
    int r  = tid >> 2;
    int g  = tid & 3;
    int qi = q0 + r;
    float rsum = 0.f;

    const float scale = 0.17677669529663689f;  // 1/sqrt(32)
    int nIter = causal ? ((qt + 2) >> 1) : (Lk >> 7);

    stage_kv(0, 0);

    for (int it = 0; it < nIter; it++) {
        int buf = it & 1;
        int k0  = it*128;
        if (it + 1 < nIter) {
            stage_kv(it+1, buf ^ 1);
            cpa_wait<1>();
        } else {
            cpa_wait<0>();
        }
        __syncthreads();

        __half* Ks = KsB[buf];
        __half* Vs = VsB[buf];

        // ---- S = Q @ K^T (64 x 128) ----
        #pragma unroll
        for (int nj = 0; nj < 4; nj++) {
            int n = sch*4 + nj;
            wmma::fragment<wmma::accumulator,16,16,16,float> cf;
            wmma::fill_fragment(cf, 0.0f);
            #pragma unroll
            for (int kk = 0; kk < 2; kk++) {
                wmma::fragment<wmma::matrix_b,16,16,16,__half,wmma::col_major> kb;
                wmma::load_matrix_sync(kb, &Ks[n*16*40 + kk*16], 40);
                wmma::mma_sync(cf, qa[kk], kb, cf);
            }
            wmma::store_matrix_sync(&Ss[smi*16*140 + n*16], cf, 140, wmma::mem_row_major);
        }
        __syncthreads();

        // ---- P = exp(scale*S) with mask (vectorized), reg rowsum ----
        {
            int valid = causal ? (qi - k0 + 1) : 128;   // cols < valid pass causal
            #pragma unroll
            for (int i = 0; i < 8; i++) {
                int c = i*16 + g*4;
                float4 v = *(float4*)&Ss[r*140 + c];
                int4  mm = *(const int4*)&smask[buf*128 + c];
                float e0 = (c+0 < valid && mm.x == 0) ? __expf(v.x*scale) : 0.f;
                float e1 = (c+1 < valid && mm.y == 0) ? __expf(v.y*scale) : 0.f;
                float e2 = (c+2 < valid && mm.z == 0) ? __expf(v.z*scale) : 0.f;
                float e3 = (c+3 < valid && mm.w == 0) ? __expf(v.w*scale) : 0.f;
                rsum += (e0 + e1) + (e2 + e3);
                __half2 h0 = __floats2half2_rn(e0, e1);
                __half2 h1 = __floats2half2_rn(e2, e3);
                float2 pk;
                pk.x = __uint_as_float(reinterpret_cast<unsigned&>(h0));
                pk.y = __uint_as_float(reinterpret_cast<unsigned&>(h1));
                *(float2*)&Ps[r*136 + c] = pk;
            }
        }
        __syncthreads();

        // ---- O += P @ V (64x128 @ 128x32) ----
        #pragma unroll
        for (int kk = 0; kk < 8; kk++) {
            wmma::fragment<wmma::matrix_a,16,16,16,__half,wmma::row_major> pa;
            wmma::load_matrix_sync(pa, &Ps[smi*16*136 + kk*16], 136);
            wmma::fragment<wmma::matrix_b,16,16,16,__half,wmma::row_major> vb;
            wmma::load_matrix_sync(vb, &Vs[(kk*16)*40 + sch*16], 40);
            wmma::mma_sync(of, pa, vb, of);
        }
        __syncthreads();
    }

    // reduce rowsum across the quad (lanes differing in bits 0,1)
    rsum += __shfl_xor_sync(0xffffffffu, rsum, 1);
    rsum += __shfl_xor_sync(0xffffffffu, rsum, 2);

    // write out: of -> Ss reused as [64][36] f32
    wmma::store_matrix_sync(&Ss[smi*16*36 + sch*16], of, 36, wmma::mem_row_major);
    __syncthreads();
    {
        float rinv = 1.0f / rsum;
        __half* op = Og + ((size_t)(b*SEQ + q0 + r))*DMODEL + h*DHEAD + g*8;
        #pragma unroll
        for (int cc = 0; cc < 8; cc++)
            op[cc] = __float2half(Ss[r*36 + g*8 + cc] * rinv);
    }
}

// ---------------- orchestration ----------------
extern "C" void kernel_launch(void* const* d_in, const int* in_sizes, int n_in,
                              void* d_out, int out_size) {
    const float* enc      = (const float*)d_in[0];
    const float* dec      = (const float*)d_in[1];
    const int*   enc_mask = (const int*)  d_in[2];
    const int*   dec_mask = (const int*)  d_in[3];
    const float* W_tgt    = (const float*)d_in[4];
    const float* b_tgt    = (const float*)d_in[5];
    const float* sa_Wq = (const float*)d_in[6];  const float* sa_bq = (const float*)d_in[7];
    const float* sa_Wk = (const float*)d_in[8];  const float* sa_bk = (const float*)d_in[9];
    const float* sa_Wv = (const float*)d_in[10]; const float* sa_bv = (const float*)d_in[11];
    const float* sa_Wo = (const float*)d_in[12]; const float* sa_bo = (const float*)d_in[13];
    const float* sa_g  = (const float*)d_in[14]; const float* sa_b  = (const float*)d_in[15];
    const float* ca_Wq = (const float*)d_in[16]; const float* ca_bq = (const float*)d_in[17];
    const float* ca_Wk = (const float*)d_in[18]; const float* ca_bk = (const float*)d_in[19];
    const float* ca_Wv = (const float*)d_in[20]; const float* ca_bv = (const float*)d_in[21];
    const float* ca_Wo = (const float*)d_in[22]; const float* ca_bo = (const float*)d_in[23];
    const float* ca_g  = (const float*)d_in[24]; const float* ca_b  = (const float*)d_in[25];
    const float* ff_W1 = (const float*)d_in[26]; const float* ff_b1 = (const float*)d_in[27];
    const float* ff_W2 = (const float*)d_in[28]; const float* ff_b2 = (const float*)d_in[29];
    const float* ff_g  = (const float*)d_in[30]; const float* ff_b  = (const float*)d_in[31];

    float* fs = nullptr;
    __half* hs = nullptr;
    cudaGetSymbolAddress((void**)&fs, g_fscratch);
    cudaGetSymbolAddress((void**)&hs, g_hscratch);
    float* X = fs + OFF_X;
    float* T = fs + OFF_T;
    __half* Xh  = hs + HOFF_XH;
    __half* ENCh= hs + HOFF_ENC;
    __half* Qh  = hs + HOFF_Q;
    __half* Kh  = hs + HOFF_K;
    __half* Vh  = hs + HOFF_V;
    __half* Ch  = hs + HOFF_C;
    __half* Hh  = hs + HOFF_H;
    __half* Wh  = hs + HOFF_W;

    __half* hsaWq = Wh + 0*WSEG;
    __half* hsaWk = Wh + 1*WSEG;
    __half* hsaWv = Wh + 2*WSEG;
    __half* hsaWo = Wh + 3*WSEG;
    __half* hcaWq = Wh + 4*WSEG;
    __half* hcaWk = Wh + 5*WSEG;
    __half* hcaWv = Wh + 6*WSEG;
    __half* hcaWo = Wh + 7*WSEG;
    __half* hffW1 = Wh + 8*WSEG;
    __half* hffW2 = hffW1 + NLAYER*DMODEL*DFF;

    cudaFuncSetAttribute(attn_kernel, cudaFuncAttributeMaxDynamicSharedMemorySize, ATTN_SMEM);
    cudaFuncSetAttribute(gemm_kernel<false,false,true >, cudaFuncAttributeMaxDynamicSharedMemorySize, GEMM_SMEM);
    cudaFuncSetAttribute(gemm_kernel<false,true ,false>, cudaFuncAttributeMaxDynamicSharedMemorySize, GEMM_SMEM);
    cudaFuncSetAttribute(gemm_kernel<true ,false,true >, cudaFuncAttributeMaxDynamicSharedMemorySize, GEMM_SMEM);

    // ---- single batched conversion launch ----
    {
        CvtAll ca;
        const float* srcs[11] = {sa_Wq, sa_Wk, sa_Wv, sa_Wo, ca_Wq, ca_Wk, ca_Wv, ca_Wo,
                                 ff_W1, ff_W2, enc};
        __half* dsts[11] = {hsaWq, hsaWk, hsaWv, hsaWo, hcaWq, hcaWk, hcaWv, hcaWo,
                            hffW1, hffW2, ENCh};
        int nF = NLAYER*DMODEL*DFF;
        int szs[11] = {WSEG,WSEG,WSEG,WSEG,WSEG,WSEG,WSEG,WSEG, nF, nF, TD};
        long total = 0;
        for (int i = 0; i < 11; i++) { ca.src[i]=srcs[i]; ca.dst[i]=dsts[i]; ca.size[i]=szs[i]; total += szs[i]; }
        int nThreads = (int)(total/4);
        cvt_all_kernel<<<(nThreads + 255)/256, 256>>>(ca);
    }

    dim3 blkG(256), blkA(256), blkR(256);
    dim3 g_rows(TOK);
    dim3 g_qkv(12, 64);
    dim3 g_256(4, 64);
    dim3 g_1024(16, 64);
    dim3 g_attn(SEQ/64, NHEAD, BATCH);

    embed_kernel<<<g_rows, blkR>>>(dec, W_tgt, b_tgt, X, Xh);

    const int WD  = DMODEL*DMODEL;
    const int W1S = DMODEL*DFF;
    const int W2S = DFF*DMODEL;

    for (int i = 0; i < NLAYER; i++) {
        // ---- self attention ----
        {
            GArgs ga;
            ga.A[0]=Xh; ga.A[1]=Xh; ga.A[2]=Xh;
            ga.W[0]=hsaWq+i*WD; ga.W[1]=hsaWk+i*WD; ga.W[2]=hsaWv+i*WD;
            ga.bi[0]=sa_bq+i*DMODEL; ga.bi[1]=sa_bk+i*DMODEL; ga.bi[2]=sa_bv+i*DMODEL;
            ga.O[0]=Qh; ga.O[1]=Kh; ga.O[2]=Vh;
            gemm_kernel<false,false,true><<<g_qkv, blkG, GEMM_SMEM>>>(ga, nullptr, DMODEL, DMODEL, 2);
        }
        attn_kernel<<<g_attn, blkA, ATTN_SMEM>>>(Qh, Kh, Vh, Ch, dec_mask, SEQ, 1);
        {
            GArgs ga{};
            ga.A[0]=Ch; ga.W[0]=hsaWo+i*WD; ga.bi[0]=sa_bo+i*DMODEL; ga.O[0]=T;
            gemm_kernel<false,true,false><<<g_256, blkG, GEMM_SMEM>>>(ga, X, DMODEL, DMODEL, 2);
        }
        ln_kernel<<<g_rows, blkR>>>(T, sa_g+i*DMODEL, sa_b+i*DMODEL, X, Xh, 0);

        // ---- cross attention ----
        {
            GArgs ga;
            ga.A[0]=Xh; ga.A[1]=ENCh; ga.A[2]=ENCh;
            ga.W[0]=hcaWq+i*WD; ga.W[1]=hcaWk+i*WD; ga.W[2]=hcaWv+i*WD;
            ga.bi[0]=ca_bq+i*DMODEL; ga.bi[1]=ca_bk+i*DMODEL; ga.bi[2]=ca_bv+i*DMODEL;
            ga.O[0]=Qh; ga.O[1]=Kh; ga.O[2]=Vh;
            gemm_kernel<false,false,true><<<g_qkv, blkG, GEMM_SMEM>>>(ga, nullptr, DMODEL, DMODEL, 2);
        }
        attn_kernel<<<g_attn, blkA, ATTN_SMEM>>>(Qh, Kh, Vh, Ch, enc_mask, SEQ, 0);
        {
            GArgs ga{};
            ga.A[0]=Ch; ga.W[0]=hcaWo+i*WD; ga.bi[0]=ca_bo+i*DMODEL; ga.O[0]=T;
            gemm_kernel<false,true,false><<<g_256, blkG, GEMM_SMEM>>>(ga, X, DMODEL, DMODEL, 2);
        }
        ln_kernel<<<g_rows, blkR>>>(T, ca_g+i*DMODEL, ca_b+i*DMODEL, X, Xh, 0);

        // ---- FFN ----
        {
            GArgs ga{};
            ga.A[0]=Xh; ga.W[0]=hffW1+i*W1S; ga.bi[0]=ff_b1+i*DFF; ga.O[0]=Hh;
            gemm_kernel<true,false,true><<<g_1024, blkG, GEMM_SMEM>>>(ga, nullptr, DMODEL, DFF, 4);
        }
        {
            GArgs ga{};
            ga.A[0]=Hh; ga.W[0]=hffW2+i*W2S; ga.bi[0]=ff_b2+i*DMODEL; ga.O[0]=T;
            gemm_kernel<false,true,false><<<g_256, blkG, GEMM_SMEM>>>(ga, X, DFF, DMODEL, 2);
        }
        ln_kernel<<<g_rows, blkR>>>(T, ff_g+i*DMODEL, ff_b+i*DMODEL, X, Xh, (i < NLAYER-1) ? 1 : 0);
    }

    cudaMemcpyAsync(d_out, X, (size_t)TD*sizeof(float),
                    cudaMemcpyDeviceToDevice);
}

// round 8
// speedup vs baseline: 1.5621x; 1.2357x over previous
#include <cuda_runtime.h>
#include <cuda_fp16.h>
#include <mma.h>
#include <math.h>

using namespace nvcuda;

#define BATCH   4
#define SEQ     1024
#define DMODEL  256
#define NHEAD   8
#define DHEAD   32
#define DFF     1024
#define NLAYER  6
#define TOK     (BATCH*SEQ)
#define TD      (TOK*DMODEL)          // 1,048,576

__device__ __align__(16) float  g_fscratch[2*TD];
__device__ __align__(16) __half g_hscratch[16*1024*1024];

#define OFF_X 0
#define OFF_T TD

#define HOFF_XH  0
#define HOFF_ENC (1*TD)
#define HOFF_Q   (2*TD)
#define HOFF_K   (3*TD)
#define HOFF_V   (4*TD)
#define HOFF_C   (5*TD)
#define HOFF_H   (6*TD)
#define HOFF_W   (10*TD)
#define WSEG     393216               // NL*256*256

// ---------------- cp.async helpers ----------------
__device__ __forceinline__ void cpa16(void* dst, const void* src) {
    unsigned s = (unsigned)__cvta_generic_to_shared(dst);
    asm volatile("cp.async.cg.shared.global [%0], [%1], 16;\n" :: "r"(s), "l"(src));
}
__device__ __forceinline__ void cpa_commit() {
    asm volatile("cp.async.commit_group;\n");
}
template<int N>
__device__ __forceinline__ void cpa_wait() {
    asm volatile("cp.async.wait_group %0;\n" :: "n"(N));
}

// ---------------- raw mma helpers ----------------
__device__ __forceinline__ void mma16816(float* c, const unsigned* a, const unsigned* b) {
    asm volatile("mma.sync.aligned.m16n8k16.row.col.f32.f16.f16.f32 "
        "{%0,%1,%2,%3}, {%4,%5,%6,%7}, {%8,%9}, {%0,%1,%2,%3};"
        : "+f"(c[0]), "+f"(c[1]), "+f"(c[2]), "+f"(c[3])
        : "r"(a[0]), "r"(a[1]), "r"(a[2]), "r"(a[3]), "r"(b[0]), "r"(b[1]));
}
__device__ __forceinline__ void ldsm4t(unsigned* r, unsigned addr) {
    asm volatile("ldmatrix.sync.aligned.m8n8.x4.trans.shared.b16 {%0,%1,%2,%3}, [%4];"
        : "=r"(r[0]), "=r"(r[1]), "=r"(r[2]), "=r"(r[3]) : "r"(addr));
}
__device__ __forceinline__ float ex2(float x) {
    float y; asm("ex2.approx.f32 %0, %1;" : "=f"(y) : "f"(x)); return y;
}

// ---------------- batched fp32 -> fp16 convert (one launch) ----------------
struct CvtAll {
    const float* src[11];
    __half*      dst[11];
    int          size[11];
};
__global__ void cvt_all_kernel(CvtAll ca) {
    long idx = ((long)blockIdx.x*blockDim.x + threadIdx.x)*4;
    #pragma unroll
    for (int s = 0; s < 11; s++) {
        if (idx < ca.size[s]) {
            float4 v = *(const float4*)&ca.src[s][idx];
            __half2* o = (__half2*)&ca.dst[s][idx];
            o[0] = __floats2half2_rn(v.x, v.y);
            o[1] = __floats2half2_rn(v.z, v.w);
            return;
        }
        idx -= ca.size[s];
    }
}

// ---------------- positional embedding ----------------
__device__ __forceinline__ float pe_val(int l, int d) {
    int j = d & 127;
    double e = -(2.0*(double)j/256.0) * 9.210340371976184;  // ln(10000)
    float invf = (float)exp(e);
    float arg = (float)l * invf;
    return (d < 128) ? sinf(arg) : cosf(arg);
}

// ---------------- embed (+PE layer 0), dual fp32/fp16 out ----------------
__global__ void embed_kernel(const float* __restrict__ dec,
                             const float* __restrict__ W,
                             const float* __restrict__ b,
                             float* __restrict__ x, __half* __restrict__ xh) {
    int row = blockIdx.x;
    int d   = threadIdx.x;
    const float* in = dec + row*3;
    float acc = b[d] + in[0]*W[d] + in[1]*W[DMODEL+d] + in[2]*W[2*DMODEL+d]
              + pe_val(row & (SEQ-1), d);
    x [row*DMODEL + d] = acc;
    xh[row*DMODEL + d] = __float2half(acc);
}

// ---------------- LayerNorm, dual out, optional +PE ----------------
__global__ void ln_kernel(const float* __restrict__ t,
                          const float* __restrict__ g,
                          const float* __restrict__ b,
                          float* __restrict__ out, __half* __restrict__ outh,
                          int addpe) {
    int row = blockIdx.x;
    int d   = threadIdx.x;
    float v = t[row*DMODEL + d];

    __shared__ float red[8];
    __shared__ float stats[2];

    float s = v;
    #pragma unroll
    for (int o = 16; o; o >>= 1) s += __shfl_xor_sync(0xffffffffu, s, o);
    if ((d & 31) == 0) red[d >> 5] = s;
    __syncthreads();
    if (d == 0) {
        float m = 0.f;
        #pragma unroll
        for (int i = 0; i < 8; i++) m += red[i];
        stats[0] = m * (1.0f/DMODEL);
    }
    __syncthreads();
    float mean = stats[0];
    float dv = v - mean;
    float s2 = dv*dv;
    #pragma unroll
    for (int o = 16; o; o >>= 1) s2 += __shfl_xor_sync(0xffffffffu, s2, o);
    if ((d & 31) == 0) red[d >> 5] = s2;
    __syncthreads();
    if (d == 0) {
        float var = 0.f;
        #pragma unroll
        for (int i = 0; i < 8; i++) var += red[i];
        stats[1] = rsqrtf(var * (1.0f/DMODEL) + 1e-5f);
    }
    __syncthreads();
    float o = dv * stats[1] * g[d] + b[d];
    if (addpe) o += pe_val(row & (SEQ-1), d);
    out [row*DMODEL + d] = o;
    outh[row*DMODEL + d] = __float2half(o);
}

// ---------------- fp16 wmma GEMM: 64x64x32, 256 thr, 3-stage ----------
struct GArgs {
    const __half* A[3];
    const __half* W[3];
    const float*  bi[3];
    void*         O[3];
};

#define AS_H 40
#define BS_H 72
#define GEMM_SMEM ((3*64*AS_H + 3*32*BS_H)*2)   // 29184 B

template<bool RELU, bool RES, bool OUTH>
__global__ __launch_bounds__(256)
void gemm_kernel(GArgs ga, const float* __restrict__ Rres,
                 int K, int N, int bnshift) {
    extern __shared__ __align__(16) char dsmc[];
    __half* As = (__half*)dsmc;
    __half* Bs = As + 3*64*AS_H;

    int tid = threadIdx.x;
    int w   = tid >> 5;
    int bx  = blockIdx.x;
    int sel = bx >> bnshift;
    int bn  = bx & ((1 << bnshift) - 1);
    int bm  = blockIdx.y;

    const __half* Abase = ga.A[sel] + (size_t)(bm*64)*K;
    const __half* Wbase = ga.W[sel] + bn*64;
    const float*  bias  = ga.bi[sel];

    int wm = w & 3;
    int wn = w >> 2;

    wmma::fragment<wmma::accumulator,16,16,16,float> c[2];
    wmma::fill_fragment(c[0], 0.0f);
    wmma::fill_fragment(c[1], 0.0f);

    auto stage = [&](int t, int buf) {
        __half* Ab = As + buf*64*AS_H;
        __half* Bb = Bs + buf*32*BS_H;
        const __half* Ag = Abase + t*32;
        {
            int r = tid >> 2, c8 = tid & 3;
            cpa16(&Ab[r*AS_H + c8*8], Ag + (size_t)r*K + c8*8);
        }
        const __half* Wg = Wbase + (size_t)(t*32)*N;
        {
            int r = tid >> 3, c8 = tid & 7;
            cpa16(&Bb[r*BS_H + c8*8], Wg + (size_t)r*N + c8*8);
        }
        cpa_commit();
    };

    int T = K >> 5;
    stage(0, 0);
    if (T > 1) stage(1, 1);

    for (int t = 0; t < T; t++) {
        if (t + 1 < T) cpa_wait<1>(); else cpa_wait<0>();
        __syncthreads();
        if (t + 2 < T) stage(t+2, (t+2)%3);

        int buf = t % 3;
        __half* Ab = As + buf*64*AS_H;
        __half* Bb = Bs + buf*32*BS_H;
        #pragma unroll
        for (int kk = 0; kk < 2; kk++) {
            wmma::fragment<wmma::matrix_a,16,16,16,__half,wmma::row_major> a;
            wmma::load_matrix_sync(a, &Ab[(wm*16)*AS_H + kk*16], AS_H);
            #pragma unroll
            for (int j = 0; j < 2; j++) {
                wmma::fragment<wmma::matrix_b,16,16,16,__half,wmma::row_major> bf;
                wmma::load_matrix_sync(bf, &Bb[(kk*16)*BS_H + wn*32 + j*16], BS_H);
                wmma::mma_sync(c[j], a, bf, c[j]);
            }
        }
    }
    __syncthreads();

    float* Cs = (float*)dsmc;   // 64 x 68 floats
    #pragma unroll
    for (int j = 0; j < 2; j++)
        wmma::store_matrix_sync(&Cs[(wm*16)*68 + wn*32 + j*16], c[j], 68,
                                wmma::mem_row_major);
    __syncthreads();

    #pragma unroll
    for (int i = 0; i < 4; i++) {
        int s = tid + i*256;
        int r = s >> 4, c4 = s & 15;
        int gr = bm*64 + r;
        int gc = bn*64 + c4*4;
        float4 v  = *(float4*)&Cs[r*68 + c4*4];
        float4 bb = *(const float4*)&bias[gc];
        v.x += bb.x; v.y += bb.y; v.z += bb.z; v.w += bb.w;
        if (RES) {
            float4 rr = *(const float4*)&Rres[(size_t)gr*N + gc];
            v.x += rr.x; v.y += rr.y; v.z += rr.z; v.w += rr.w;
        }
        if (RELU) {
            v.x = fmaxf(v.x, 0.f); v.y = fmaxf(v.y, 0.f);
            v.z = fmaxf(v.z, 0.f); v.w = fmaxf(v.w, 0.f);
        }
        if (OUTH) {
            __half2* op = (__half2*)((__half*)ga.O[sel] + (size_t)gr*N + gc);
            op[0] = __floats2half2_rn(v.x, v.y);
            op[1] = __floats2half2_rn(v.z, v.w);
        } else {
            *(float4*)((float*)ga.O[sel] + (size_t)gr*N + gc) = v;
        }
    }
}

// ---------------- fused attention v3: register-resident softmax (raw mma) -------
// 64 q-rows/CTA, 128-key tiles, 8 warps: m-tile = w&3 (16 rows), key-half = w>>2 (64 keys).
// smem: Qs 64x40h @0 (5120) | Ks dbuf 128x40h @5120/@15360 | Vs dbuf @25600/@35840
//       | smask 2x128 int @46080 (1024).  Total 47104 B -> 4 CTAs/SM.
// Epilogue reuses smc[0..8448) for cross-warp O/rowsum merge.
#define ATTN_SMEM 47104

__global__ __launch_bounds__(256)
void attn_kernel(const __half* __restrict__ Qg, const __half* __restrict__ Kg,
                 const __half* __restrict__ Vg, __half* __restrict__ Og,
                 const int* __restrict__ mask, int Lk, int causal) {
    extern __shared__ __align__(16) char smc[];
    __half* Qs     = (__half*)smc;
    __half* KsB[2] = {(__half*)(smc + 5120),  (__half*)(smc + 15360)};
    __half* VsB[2] = {(__half*)(smc + 25600), (__half*)(smc + 35840)};
    int*    smask  = (int*)(smc + 46080);

    int tid = threadIdx.x, w = tid >> 5, lane = tid & 31;
    int qt = blockIdx.x, h = blockIdx.y, b = blockIdx.z;
    int q0 = qt*64;
    int mi = w & 3, kh = w >> 2;
    int r  = lane >> 2, g = lane & 3;

    // load Q tile (64x32 halves)
    const __half* Qp = Qg + ((size_t)(b*SEQ + q0))*DMODEL + h*DHEAD;
    {
        int rr = tid >> 2, c8 = tid & 3;
        *(float4*)&Qs[rr*40 + c8*8] = *(const float4*)&Qp[(size_t)rr*DMODEL + c8*8];
    }

    auto stage_kv = [&](int it, int buf) {
        int k0 = it*128;
        const __half* Kp = Kg + ((size_t)(b*Lk + k0))*DMODEL + h*DHEAD;
        const __half* Vp = Vg + ((size_t)(b*Lk + k0))*DMODEL + h*DHEAD;
        #pragma unroll
        for (int i = 0; i < 2; i++) {
            int s = tid + i*256;
            int rr = s >> 2, c8 = s & 3;
            cpa16(&KsB[buf][rr*40 + c8*8], Kp + (size_t)rr*DMODEL + c8*8);
            cpa16(&VsB[buf][rr*40 + c8*8], Vp + (size_t)rr*DMODEL + c8*8);
        }
        if (tid < 128) smask[buf*128 + tid] = mask[b*Lk + k0 + tid];
        cpa_commit();
    };

    stage_kv(0, 0);
    __syncthreads();   // Qs visible

    // persistent Q A-fragments (m16 x k32 = two k16 frags); documented m16n8k16 layout
    unsigned qa[2][4];
    #pragma unroll
    for (int kk = 0; kk < 2; kk++) {
        const __half* base = &Qs[(mi*16 + r)*40 + kk*16 + g*2];
        qa[kk][0] = *(const unsigned*)(base);
        qa[kk][1] = *(const unsigned*)(base + 8*40);
        qa[kk][2] = *(const unsigned*)(base + 8);
        qa[kk][3] = *(const unsigned*)(base + 8*40 + 8);
    }

    float oc[4][4];
    #pragma unroll
    for (int v = 0; v < 4; v++)
        #pragma unroll
        for (int e = 0; e < 4; e++) oc[v][e] = 0.f;
    float rs0 = 0.f, rs1 = 0.f;

    int qi0 = q0 + mi*16 + r;          // row of c0/c1; c2/c3 at qi0+8
    const float sc2 = 0.17677669529663689f * 1.4426950408889634f;  // (1/sqrt32)*log2(e)
    int nIter = causal ? ((qt + 2) >> 1) : (Lk >> 7);
    int kwbase = kh*64;

    for (int it = 0; it < nIter; it++) {
        int buf = it & 1;
        int k0  = it*128;
        cpa_wait<0>();
        __syncthreads();                      // data visible + all warps done with buf^1
        if (it + 1 < nIter) stage_kv(it+1, buf ^ 1);

        const __half* Ks = KsB[buf];
        const __half* Vs = VsB[buf];

        #pragma unroll
        for (int tq = 0; tq < 4; tq++) {      // key pairs j = 2tq, 2tq+1 (16 keys)
            unsigned pa[4];
            #pragma unroll
            for (int jj = 0; jj < 2; jj++) {
                int j = tq*2 + jj;
                float cf[4] = {0.f, 0.f, 0.f, 0.f};
                const __half* kb0 = &Ks[(kwbase + j*8 + r)*40 + g*2];
                #pragma unroll
                for (int s = 0; s < 2; s++) {
                    unsigned bb[2];
                    bb[0] = *(const unsigned*)(kb0 + s*16);
                    bb[1] = *(const unsigned*)(kb0 + s*16 + 8);
                    mma16816(cf, qa[s], bb);
                }
                // softmax in registers
                int jcol = kwbase + j*8 + g*2;
                int2 mm = *(const int2*)&smask[buf*128 + jcol];
                int kgc = k0 + jcol;
                float e0, e1, e2, e3;
                if (causal) {
                    e0 = (kgc   <= qi0   && mm.x == 0) ? ex2(cf[0]*sc2) : 0.f;
                    e1 = (kgc+1 <= qi0   && mm.y == 0) ? ex2(cf[1]*sc2) : 0.f;
                    e2 = (kgc   <= qi0+8 && mm.x == 0) ? ex2(cf[2]*sc2) : 0.f;
                    e3 = (kgc+1 <= qi0+8 && mm.y == 0) ? ex2(cf[3]*sc2) : 0.f;
                } else {
                    e0 = (mm.x == 0) ? ex2(cf[0]*sc2) : 0.f;
                    e1 = (mm.y == 0) ? ex2(cf[1]*sc2) : 0.f;
                    e2 = (mm.x == 0) ? ex2(cf[2]*sc2) : 0.f;
                    e3 = (mm.y == 0) ? ex2(cf[3]*sc2) : 0.f;
                }
                rs0 += e0 + e1;
                rs1 += e2 + e3;
                __half2 plo = __floats2half2_rn(e0, e1);
                __half2 phi = __floats2half2_rn(e2, e3);
                pa[jj*2 + 0] = reinterpret_cast<unsigned&>(plo);
                pa[jj*2 + 1] = reinterpret_cast<unsigned&>(phi);
            }
            // V B-fragments for this k16 block via 2x ldmatrix.x4.trans
            int kb = kwbase + tq*16;
            unsigned vb[8];
            {
                int rowoff = lane & 15;
                int coloff = (lane >> 4) * 8;
                ldsm4t(vb,     (unsigned)__cvta_generic_to_shared(&Vs[(kb + rowoff)*40 + coloff]));
                ldsm4t(vb + 4, (unsigned)__cvta_generic_to_shared(&Vs[(kb + rowoff)*40 + 16 + coloff]));
            }
            #pragma unroll
            for (int v = 0; v < 4; v++)
                mma16816(oc[v], pa, &vb[v*2]);
        }
    }

    // quad-reduce rowsums (cols are spread over lane&3)
    rs0 += __shfl_xor_sync(0xffffffffu, rs0, 1);
    rs0 += __shfl_xor_sync(0xffffffffu, rs0, 2);
    rs1 += __shfl_xor_sync(0xffffffffu, rs1, 1);
    rs1 += __shfl_xor_sync(0xffffffffu, rs1, 2);

    // merge key-halves: upper warps (kh=1) publish partials, lower warps finalize
    __syncthreads();
    float* Ored = (float*)smc;            // 64*32 f32 = 8192 B
    float* rsS  = (float*)(smc + 8192);   // 64 f32
    if (kh == 1) {
        #pragma unroll
        for (int v = 0; v < 4; v++) {
            int cc = v*8 + g*2;
            Ored[(mi*16 + r)*32 + cc]       = oc[v][0];
            Ored[(mi*16 + r)*32 + cc + 1]   = oc[v][1];
            Ored[(mi*16 + r + 8)*32 + cc]   = oc[v][2];
            Ored[(mi*16 + r + 8)*32 + cc+1] = oc[v][3];
        }
        if (g == 0) { rsS[mi*16 + r] = rs0; rsS[mi*16 + r + 8] = rs1; }
    }
    __syncthreads();
    if (kh == 0) {
        float rt0 = 1.f / (rs0 + rsS[mi*16 + r]);
        float rt1 = 1.f / (rs1 + rsS[mi*16 + r + 8]);
        __half* o0 = Og + ((size_t)(b*SEQ + q0 + mi*16 + r))*DMODEL + h*DHEAD;
        __half* o1 = o0 + (size_t)8*DMODEL;
        #pragma unroll
        for (int v = 0; v < 4; v++) {
            int cc = v*8 + g*2;
            float p00 = (oc[v][0] + Ored[(mi*16 + r)*32 + cc])     * rt0;
            float p01 = (oc[v][1] + Ored[(mi*16 + r)*32 + cc + 1]) * rt0;
            float p10 = (oc[v][2] + Ored[(mi*16 + r + 8)*32 + cc])     * rt1;
            float p11 = (oc[v][3] + Ored[(mi*16 + r + 8)*32 + cc + 1]) * rt1;
            *(__half2*)(o0 + cc) = __floats2half2_rn(p00, p01);
            *(__half2*)(o1 + cc) = __floats2half2_rn(p10, p11);
        }
    }
}

// ---------------- orchestration ----------------
extern "C" void kernel_launch(void* const* d_in, const int* in_sizes, int n_in,
                              void* d_out, int out_size) {
    const float* enc      = (const float*)d_in[0];
    const float* dec      = (const float*)d_in[1];
    const int*   enc_mask = (const int*)  d_in[2];
    const int*   dec_mask = (const int*)  d_in[3];
    const float* W_tgt    = (const float*)d_in[4];
    const float* b_tgt    = (const float*)d_in[5];
    const float* sa_Wq = (const float*)d_in[6];  const float* sa_bq = (const float*)d_in[7];
    const float* sa_Wk = (const float*)d_in[8];  const float* sa_bk = (const float*)d_in[9];
    const float* sa_Wv = (const float*)d_in[10]; const float* sa_bv = (const float*)d_in[11];
    const float* sa_Wo = (const float*)d_in[12]; const float* sa_bo = (const float*)d_in[13];
    const float* sa_g  = (const float*)d_in[14]; const float* sa_b  = (const float*)d_in[15];
    const float* ca_Wq = (const float*)d_in[16]; const float* ca_bq = (const float*)d_in[17];
    const float* ca_Wk = (const float*)d_in[18]; const float* ca_bk = (const float*)d_in[19];
    const float* ca_Wv = (const float*)d_in[20]; const float* ca_bv = (const float*)d_in[21];
    const float* ca_Wo = (const float*)d_in[22]; const float* ca_bo = (const float*)d_in[23];
    const float* ca_g  = (const float*)d_in[24]; const float* ca_b  = (const float*)d_in[25];
    const float* ff_W1 = (const float*)d_in[26]; const float* ff_b1 = (const float*)d_in[27];
    const float* ff_W2 = (const float*)d_in[28]; const float* ff_b2 = (const float*)d_in[29];
    const float* ff_g  = (const float*)d_in[30]; const float* ff_b  = (const float*)d_in[31];

    float* fs = nullptr;
    __half* hs = nullptr;
    cudaGetSymbolAddress((void**)&fs, g_fscratch);
    cudaGetSymbolAddress((void**)&hs, g_hscratch);
    float* X = fs + OFF_X;
    float* T = fs + OFF_T;
    __half* Xh  = hs + HOFF_XH;
    __half* ENCh= hs + HOFF_ENC;
    __half* Qh  = hs + HOFF_Q;
    __half* Kh  = hs + HOFF_K;
    __half* Vh  = hs + HOFF_V;
    __half* Ch  = hs + HOFF_C;
    __half* Hh  = hs + HOFF_H;
    __half* Wh  = hs + HOFF_W;

    __half* hsaWq = Wh + 0*WSEG;
    __half* hsaWk = Wh + 1*WSEG;
    __half* hsaWv = Wh + 2*WSEG;
    __half* hsaWo = Wh + 3*WSEG;
    __half* hcaWq = Wh + 4*WSEG;
    __half* hcaWk = Wh + 5*WSEG;
    __half* hcaWv = Wh + 6*WSEG;
    __half* hcaWo = Wh + 7*WSEG;
    __half* hffW1 = Wh + 8*WSEG;
    __half* hffW2 = hffW1 + NLAYER*DMODEL*DFF;

    cudaFuncSetAttribute(attn_kernel, cudaFuncAttributeMaxDynamicSharedMemorySize, ATTN_SMEM);
    cudaFuncSetAttribute(gemm_kernel<false,false,true >, cudaFuncAttributeMaxDynamicSharedMemorySize, GEMM_SMEM);
    cudaFuncSetAttribute(gemm_kernel<false,true ,false>, cudaFuncAttributeMaxDynamicSharedMemorySize, GEMM_SMEM);
    cudaFuncSetAttribute(gemm_kernel<true ,false,true >, cudaFuncAttributeMaxDynamicSharedMemorySize, GEMM_SMEM);

    // ---- single batched conversion launch ----
    {
        CvtAll ca;
        const float* srcs[11] = {sa_Wq, sa_Wk, sa_Wv, sa_Wo, ca_Wq, ca_Wk, ca_Wv, ca_Wo,
                                 ff_W1, ff_W2, enc};
        __half* dsts[11] = {hsaWq, hsaWk, hsaWv, hsaWo, hcaWq, hcaWk, hcaWv, hcaWo,
                            hffW1, hffW2, ENCh};
        int nF = NLAYER*DMODEL*DFF;
        int szs[11] = {WSEG,WSEG,WSEG,WSEG,WSEG,WSEG,WSEG,WSEG, nF, nF, TD};
        long total = 0;
        for (int i = 0; i < 11; i++) { ca.src[i]=srcs[i]; ca.dst[i]=dsts[i]; ca.size[i]=szs[i]; total += szs[i]; }
        int nThreads = (int)(total/4);
        cvt_all_kernel<<<(nThreads + 255)/256, 256>>>(ca);
    }

    dim3 blkG(256), blkA(256), blkR(256);
    dim3 g_rows(TOK);
    dim3 g_qkv(12, 64);
    dim3 g_256(4, 64);
    dim3 g_1024(16, 64);
    dim3 g_attn(SEQ/64, NHEAD, BATCH);

    embed_kernel<<<g_rows, blkR>>>(dec, W_tgt, b_tgt, X, Xh);

    const int WD  = DMODEL*DMODEL;
    const int W1S = DMODEL*DFF;
    const int W2S = DFF*DMODEL;

    for (int i = 0; i < NLAYER; i++) {
        // ---- self attention ----
        {
            GArgs ga;
            ga.A[0]=Xh; ga.A[1]=Xh; ga.A[2]=Xh;
            ga.W[0]=hsaWq+i*WD; ga.W[1]=hsaWk+i*WD; ga.W[2]=hsaWv+i*WD;
            ga.bi[0]=sa_bq+i*DMODEL; ga.bi[1]=sa_bk+i*DMODEL; ga.bi[2]=sa_bv+i*DMODEL;
            ga.O[0]=Qh; ga.O[1]=Kh; ga.O[2]=Vh;
            gemm_kernel<false,false,true><<<g_qkv, blkG, GEMM_SMEM>>>(ga, nullptr, DMODEL, DMODEL, 2);
        }
        attn_kernel<<<g_attn, blkA, ATTN_SMEM>>>(Qh, Kh, Vh, Ch, dec_mask, SEQ, 1);
        {
            GArgs ga{};
            ga.A[0]=Ch; ga.W[0]=hsaWo+i*WD; ga.bi[0]=sa_bo+i*DMODEL; ga.O[0]=T;
            gemm_kernel<false,true,false><<<g_256, blkG, GEMM_SMEM>>>(ga, X, DMODEL, DMODEL, 2);
        }
        ln_kernel<<<g_rows, blkR>>>(T, sa_g+i*DMODEL, sa_b+i*DMODEL, X, Xh, 0);

        // ---- cross attention ----
        {
            GArgs ga;
            ga.A[0]=Xh; ga.A[1]=ENCh; ga.A[2]=ENCh;
            ga.W[0]=hcaWq+i*WD; ga.W[1]=hcaWk+i*WD; ga.W[2]=hcaWv+i*WD;
            ga.bi[0]=ca_bq+i*DMODEL; ga.bi[1]=ca_bk+i*DMODEL; ga.bi[2]=ca_bv+i*DMODEL;
            ga.O[0]=Qh; ga.O[1]=Kh; ga.O[2]=Vh;
            gemm_kernel<false,false,true><<<g_qkv, blkG, GEMM_SMEM>>>(ga, nullptr, DMODEL, DMODEL, 2);
        }
        attn_kernel<<<g_attn, blkA, ATTN_SMEM>>>(Qh, Kh, Vh, Ch, enc_mask, SEQ, 0);
        {
            GArgs ga{};
            ga.A[0]=Ch; ga.W[0]=hcaWo+i*WD; ga.bi[0]=ca_bo+i*DMODEL; ga.O[0]=T;
            gemm_kernel<false,true,false><<<g_256, blkG, GEMM_SMEM>>>(ga, X, DMODEL, DMODEL, 2);
        }
        ln_kernel<<<g_rows, blkR>>>(T, ca_g+i*DMODEL, ca_b+i*DMODEL, X, Xh, 0);

        // ---- FFN ----
        {
            GArgs ga{};
            ga.A[0]=Xh; ga.W[0]=hffW1+i*W1S; ga.bi[0]=ff_b1+i*DFF; ga.O[0]=Hh;
            gemm_kernel<true,false,true><<<g_1024, blkG, GEMM_SMEM>>>(ga, nullptr, DMODEL, DFF, 4);
        }
        {
            GArgs ga{};
            ga.A[0]=Hh; ga.W[0]=hffW2+i*W2S; ga.bi[0]=ff_b2+i*DMODEL; ga.O[0]=T;
            gemm_kernel<false,true,false><<<g_256, blkG, GEMM_SMEM>>>(ga, X, DFF, DMODEL, 2);
        }
        ln_kernel<<<g_rows, blkR>>>(T, ff_g+i*DMODEL, ff_b+i*DMODEL, X, Xh, (i < NLAYER-1) ? 1 : 0);
    }

    cudaMemcpyAsync(d_out, X, (size_t)TD*sizeof(float),
                    cudaMemcpyDeviceToDevice);
}

// round 9
// speedup vs baseline: 1.6385x; 1.0489x over previous
#include <cuda_runtime.h>
#include <cuda_fp16.h>
#include <mma.h>
#include <math.h>

using namespace nvcuda;

#define BATCH   4
#define SEQ     1024
#define DMODEL  256
#define NHEAD   8
#define DHEAD   32
#define DFF     1024
#define NLAYER  6
#define TOK     (BATCH*SEQ)
#define TD      (TOK*DMODEL)          // 1,048,576

__device__ __align__(16) float  g_fscratch[2*TD];
__device__ __align__(16) __half g_hscratch[16*1024*1024];

#define OFF_X 0
#define OFF_T TD

#define HOFF_XH  0
#define HOFF_ENC (1*TD)
#define HOFF_Q   (2*TD)
#define HOFF_K   (3*TD)
#define HOFF_V   (4*TD)
#define HOFF_C   (5*TD)
#define HOFF_H   (6*TD)
#define HOFF_W   (10*TD)
#define WSEG     393216               // NL*256*256

// ---------------- cp.async helpers ----------------
__device__ __forceinline__ void cpa16(void* dst, const void* src) {
    unsigned s = (unsigned)__cvta_generic_to_shared(dst);
    asm volatile("cp.async.cg.shared.global [%0], [%1], 16;\n" :: "r"(s), "l"(src));
}
__device__ __forceinline__ void cpa_commit() {
    asm volatile("cp.async.commit_group;\n");
}
template<int N>
__device__ __forceinline__ void cpa_wait() {
    asm volatile("cp.async.wait_group %0;\n" :: "n"(N));
}

// ---------------- raw mma helpers ----------------
__device__ __forceinline__ void mma16816(float* c, const unsigned* a, const unsigned* b) {
    asm volatile("mma.sync.aligned.m16n8k16.row.col.f32.f16.f16.f32 "
        "{%0,%1,%2,%3}, {%4,%5,%6,%7}, {%8,%9}, {%0,%1,%2,%3};"
        : "+f"(c[0]), "+f"(c[1]), "+f"(c[2]), "+f"(c[3])
        : "r"(a[0]), "r"(a[1]), "r"(a[2]), "r"(a[3]), "r"(b[0]), "r"(b[1]));
}
__device__ __forceinline__ void ldsm4t(unsigned* r, unsigned addr) {
    asm volatile("ldmatrix.sync.aligned.m8n8.x4.trans.shared.b16 {%0,%1,%2,%3}, [%4];"
        : "=r"(r[0]), "=r"(r[1]), "=r"(r[2]), "=r"(r[3]) : "r"(addr));
}
__device__ __forceinline__ float ex2(float x) {
    float y; asm("ex2.approx.f32 %0, %1;" : "=f"(y) : "f"(x)); return y;
}

// ---------------- batched fp32 -> fp16 convert (one launch) ----------------
struct CvtAll {
    const float* src[11];
    __half*      dst[11];
    int          size[11];
};
__global__ void cvt_all_kernel(CvtAll ca) {
    long idx = ((long)blockIdx.x*blockDim.x + threadIdx.x)*4;
    #pragma unroll
    for (int s = 0; s < 11; s++) {
        if (idx < ca.size[s]) {
            float4 v = *(const float4*)&ca.src[s][idx];
            __half2* o = (__half2*)&ca.dst[s][idx];
            o[0] = __floats2half2_rn(v.x, v.y);
            o[1] = __floats2half2_rn(v.z, v.w);
            return;
        }
        idx -= ca.size[s];
    }
}

// ---------------- positional embedding ----------------
__device__ __forceinline__ float pe_val(int l, int d) {
    int j = d & 127;
    double e = -(2.0*(double)j/256.0) * 9.210340371976184;  // ln(10000)
    float invf = (float)exp(e);
    float arg = (float)l * invf;
    return (d < 128) ? sinf(arg) : cosf(arg);
}

// ---------------- embed (+PE layer 0), dual fp32/fp16 out ----------------
__global__ void embed_kernel(const float* __restrict__ dec,
                             const float* __restrict__ W,
                             const float* __restrict__ b,
                             float* __restrict__ x, __half* __restrict__ xh) {
    int row = blockIdx.x;
    int d   = threadIdx.x;
    const float* in = dec + row*3;
    float acc = b[d] + in[0]*W[d] + in[1]*W[DMODEL+d] + in[2]*W[2*DMODEL+d]
              + pe_val(row & (SEQ-1), d);
    x [row*DMODEL + d] = acc;
    xh[row*DMODEL + d] = __float2half(acc);
}

// ---------------- LayerNorm, dual out, optional +PE ----------------
__global__ void ln_kernel(const float* __restrict__ t,
                          const float* __restrict__ g,
                          const float* __restrict__ b,
                          float* __restrict__ out, __half* __restrict__ outh,
                          int addpe) {
    int row = blockIdx.x;
    int d   = threadIdx.x;
    float v = t[row*DMODEL + d];

    __shared__ float red[8];
    __shared__ float stats[2];

    float s = v;
    #pragma unroll
    for (int o = 16; o; o >>= 1) s += __shfl_xor_sync(0xffffffffu, s, o);
    if ((d & 31) == 0) red[d >> 5] = s;
    __syncthreads();
    if (d == 0) {
        float m = 0.f;
        #pragma unroll
        for (int i = 0; i < 8; i++) m += red[i];
        stats[0] = m * (1.0f/DMODEL);
    }
    __syncthreads();
    float mean = stats[0];
    float dv = v - mean;
    float s2 = dv*dv;
    #pragma unroll
    for (int o = 16; o; o >>= 1) s2 += __shfl_xor_sync(0xffffffffu, s2, o);
    if ((d & 31) == 0) red[d >> 5] = s2;
    __syncthreads();
    if (d == 0) {
        float var = 0.f;
        #pragma unroll
        for (int i = 0; i < 8; i++) var += red[i];
        stats[1] = rsqrtf(var * (1.0f/DMODEL) + 1e-5f);
    }
    __syncthreads();
    float o = dv * stats[1] * g[d] + b[d];
    if (addpe) o += pe_val(row & (SEQ-1), d);
    out [row*DMODEL + d] = o;
    outh[row*DMODEL + d] = __float2half(o);
}

// ---------------- fp16 wmma GEMM v2: 64x128x32, 256 thr, warp 32x32, 3-stage ------
struct GArgs {
    const __half* A[3];
    const __half* W[3];
    const float*  bi[3];
    void*         O[3];
};

#define AS_H 40      // A tile stride (64 rows x 32 halves)
#define BS_H 136     // B tile stride (32 rows x 128 halves)
#define GEMM_SMEM ((3*64*AS_H + 3*32*BS_H)*2)   // 41472 B

template<bool RELU, bool RES, bool OUTH>
__global__ __launch_bounds__(256)
void gemm_kernel(GArgs ga, const float* __restrict__ Rres,
                 int K, int N, int bnshift) {
    extern __shared__ __align__(16) char dsmc[];
    __half* As = (__half*)dsmc;            // 3 x 64*AS_H
    __half* Bs = As + 3*64*AS_H;           // 3 x 32*BS_H

    int tid = threadIdx.x;
    int w   = tid >> 5;
    int bx  = blockIdx.x;
    int sel = bx >> bnshift;
    int bn  = bx & ((1 << bnshift) - 1);
    int bm  = blockIdx.y;

    const __half* Abase = ga.A[sel] + (size_t)(bm*64)*K;
    const __half* Wbase = ga.W[sel] + bn*128;
    const float*  bias  = ga.bi[sel];

    int wm = w & 1;      // 2 row blocks of 32
    int wn = w >> 1;     // 4 col blocks of 32

    wmma::fragment<wmma::accumulator,16,16,16,float> c[2][2];
    #pragma unroll
    for (int i = 0; i < 2; i++)
        #pragma unroll
        for (int j = 0; j < 2; j++)
            wmma::fill_fragment(c[i][j], 0.0f);

    auto stage = [&](int t, int buf) {
        __half* Ab = As + buf*64*AS_H;
        __half* Bb = Bs + buf*32*BS_H;
        const __half* Ag = Abase + t*32;
        {   // A: 64 rows x 4 chunks of 8 halves
            int r = tid >> 2, c8 = tid & 3;
            cpa16(&Ab[r*AS_H + c8*8], Ag + (size_t)r*K + c8*8);
        }
        const __half* Wg = Wbase + (size_t)(t*32)*N;
        #pragma unroll
        for (int i = 0; i < 2; i++) {  // B: 32 rows x 16 chunks of 8 halves
            int s = tid + i*256;
            int r = s >> 4, c8 = s & 15;
            cpa16(&Bb[r*BS_H + c8*8], Wg + (size_t)r*N + c8*8);
        }
        cpa_commit();
    };

    int T = K >> 5;
    stage(0, 0);
    if (T > 1) stage(1, 1);

    for (int t = 0; t < T; t++) {
        if (t + 1 < T) cpa_wait<1>(); else cpa_wait<0>();
        __syncthreads();
        if (t + 2 < T) stage(t+2, (t+2)%3);

        int buf = t % 3;
        __half* Ab = As + buf*64*AS_H;
        __half* Bb = Bs + buf*32*BS_H;
        #pragma unroll
        for (int kk = 0; kk < 2; kk++) {
            wmma::fragment<wmma::matrix_a,16,16,16,__half,wmma::row_major> a[2];
            #pragma unroll
            for (int i = 0; i < 2; i++)
                wmma::load_matrix_sync(a[i], &Ab[(wm*32 + i*16)*AS_H + kk*16], AS_H);
            #pragma unroll
            for (int j = 0; j < 2; j++) {
                wmma::fragment<wmma::matrix_b,16,16,16,__half,wmma::row_major> bf;
                wmma::load_matrix_sync(bf, &Bb[(kk*16)*BS_H + wn*32 + j*16], BS_H);
                #pragma unroll
                for (int i = 0; i < 2; i++)
                    wmma::mma_sync(c[i][j], a[i], bf, c[i][j]);
            }
        }
    }
    __syncthreads();

    float* Cs = (float*)dsmc;   // 64 x 136 floats = 34816 B <= 41472
    #pragma unroll
    for (int i = 0; i < 2; i++)
        #pragma unroll
        for (int j = 0; j < 2; j++)
            wmma::store_matrix_sync(&Cs[(wm*32 + i*16)*136 + wn*32 + j*16],
                                    c[i][j], 136, wmma::mem_row_major);
    __syncthreads();

    #pragma unroll
    for (int i = 0; i < 8; i++) {
        int s = tid + i*256;            // 2048 float4 slots (64 x 32)
        int r = s >> 5, c4 = s & 31;
        int gr = bm*64 + r;
        int gc = bn*128 + c4*4;
        float4 v  = *(float4*)&Cs[r*136 + c4*4];
        float4 bb = *(const float4*)&bias[gc];
        v.x += bb.x; v.y += bb.y; v.z += bb.z; v.w += bb.w;
        if (RES) {
            float4 rr = *(const float4*)&Rres[(size_t)gr*N + gc];
            v.x += rr.x; v.y += rr.y; v.z += rr.z; v.w += rr.w;
        }
        if (RELU) {
            v.x = fmaxf(v.x, 0.f); v.y = fmaxf(v.y, 0.f);
            v.z = fmaxf(v.z, 0.f); v.w = fmaxf(v.w, 0.f);
        }
        if (OUTH) {
            __half2* op = (__half2*)((__half*)ga.O[sel] + (size_t)gr*N + gc);
            op[0] = __floats2half2_rn(v.x, v.y);
            op[1] = __floats2half2_rn(v.z, v.w);
        } else {
            *(float4*)((float*)ga.O[sel] + (size_t)gr*N + gc) = v;
        }
    }
}

// ---------------- fused attention v3: register-resident softmax (raw mma) -------
#define ATTN_SMEM 47104

__global__ __launch_bounds__(256)
void attn_kernel(const __half* __restrict__ Qg, const __half* __restrict__ Kg,
                 const __half* __restrict__ Vg, __half* __restrict__ Og,
                 const int* __restrict__ mask, int Lk, int causal) {
    extern __shared__ __align__(16) char smc[];
    __half* Qs     = (__half*)smc;
    __half* KsB[2] = {(__half*)(smc + 5120),  (__half*)(smc + 15360)};
    __half* VsB[2] = {(__half*)(smc + 25600), (__half*)(smc + 35840)};
    int*    smask  = (int*)(smc + 46080);

    int tid = threadIdx.x, w = tid >> 5, lane = tid & 31;
    int qt = blockIdx.x, h = blockIdx.y, b = blockIdx.z;
    int q0 = qt*64;
    int mi = w & 3, kh = w >> 2;
    int r  = lane >> 2, g = lane & 3;

    const __half* Qp = Qg + ((size_t)(b*SEQ + q0))*DMODEL + h*DHEAD;
    {
        int rr = tid >> 2, c8 = tid & 3;
        *(float4*)&Qs[rr*40 + c8*8] = *(const float4*)&Qp[(size_t)rr*DMODEL + c8*8];
    }

    auto stage_kv = [&](int it, int buf) {
        int k0 = it*128;
        const __half* Kp = Kg + ((size_t)(b*Lk + k0))*DMODEL + h*DHEAD;
        const __half* Vp = Vg + ((size_t)(b*Lk + k0))*DMODEL + h*DHEAD;
        #pragma unroll
        for (int i = 0; i < 2; i++) {
            int s = tid + i*256;
            int rr = s >> 2, c8 = s & 3;
            cpa16(&KsB[buf][rr*40 + c8*8], Kp + (size_t)rr*DMODEL + c8*8);
            cpa16(&VsB[buf][rr*40 + c8*8], Vp + (size_t)rr*DMODEL + c8*8);
        }
        if (tid < 128) smask[buf*128 + tid] = mask[b*Lk + k0 + tid];
        cpa_commit();
    };

    stage_kv(0, 0);
    __syncthreads();

    unsigned qa[2][4];
    #pragma unroll
    for (int kk = 0; kk < 2; kk++) {
        const __half* base = &Qs[(mi*16 + r)*40 + kk*16 + g*2];
        qa[kk][0] = *(const unsigned*)(base);
        qa[kk][1] = *(const unsigned*)(base + 8*40);
        qa[kk][2] = *(const unsigned*)(base + 8);
        qa[kk][3] = *(const unsigned*)(base + 8*40 + 8);
    }

    float oc[4][4];
    #pragma unroll
    for (int v = 0; v < 4; v++)
        #pragma unroll
        for (int e = 0; e < 4; e++) oc[v][e] = 0.f;
    float rs0 = 0.f, rs1 = 0.f;

    int qi0 = q0 + mi*16 + r;
    const float sc2 = 0.17677669529663689f * 1.4426950408889634f;
    int nIter = causal ? ((qt + 2) >> 1) : (Lk >> 7);
    int kwbase = kh*64;

    for (int it = 0; it < nIter; it++) {
        int buf = it & 1;
        int k0  = it*128;
        cpa_wait<0>();
        __syncthreads();
        if (it + 1 < nIter) stage_kv(it+1, buf ^ 1);

        const __half* Ks = KsB[buf];
        const __half* Vs = VsB[buf];

        #pragma unroll
        for (int tq = 0; tq < 4; tq++) {
            unsigned pa[4];
            #pragma unroll
            for (int jj = 0; jj < 2; jj++) {
                int j = tq*2 + jj;
                float cf[4] = {0.f, 0.f, 0.f, 0.f};
                const __half* kb0 = &Ks[(kwbase + j*8 + r)*40 + g*2];
                #pragma unroll
                for (int s = 0; s < 2; s++) {
                    unsigned bb[2];
                    bb[0] = *(const unsigned*)(kb0 + s*16);
                    bb[1] = *(const unsigned*)(kb0 + s*16 + 8);
                    mma16816(cf, qa[s], bb);
                }
                int jcol = kwbase + j*8 + g*2;
                int2 mm = *(const int2*)&smask[buf*128 + jcol];
                int kgc = k0 + jcol;
                float e0, e1, e2, e3;
                if (causal) {
                    e0 = (kgc   <= qi0   && mm.x == 0) ? ex2(cf[0]*sc2) : 0.f;
                    e1 = (kgc+1 <= qi0   && mm.y == 0) ? ex2(cf[1]*sc2) : 0.f;
                    e2 = (kgc   <= qi0+8 && mm.x == 0) ? ex2(cf[2]*sc2) : 0.f;
                    e3 = (kgc+1 <= qi0+8 && mm.y == 0) ? ex2(cf[3]*sc2) : 0.f;
                } else {
                    e0 = (mm.x == 0) ? ex2(cf[0]*sc2) : 0.f;
                    e1 = (mm.y == 0) ? ex2(cf[1]*sc2) : 0.f;
                    e2 = (mm.x == 0) ? ex2(cf[2]*sc2) : 0.f;
                    e3 = (mm.y == 0) ? ex2(cf[3]*sc2) : 0.f;
                }
                rs0 += e0 + e1;
                rs1 += e2 + e3;
                __half2 plo = __floats2half2_rn(e0, e1);
                __half2 phi = __floats2half2_rn(e2, e3);
                pa[jj*2 + 0] = reinterpret_cast<unsigned&>(plo);
                pa[jj*2 + 1] = reinterpret_cast<unsigned&>(phi);
            }
            int kb = kwbase + tq*16;
            unsigned vb[8];
            {
                int rowoff = lane & 15;
                int coloff = (lane >> 4) * 8;
                ldsm4t(vb,     (unsigned)__cvta_generic_to_shared(&Vs[(kb + rowoff)*40 + coloff]));
                ldsm4t(vb + 4, (unsigned)__cvta_generic_to_shared(&Vs[(kb + rowoff)*40 + 16 + coloff]));
            }
            #pragma unroll
            for (int v = 0; v < 4; v++)
                mma16816(oc[v], pa, &vb[v*2]);
        }
    }

    rs0 += __shfl_xor_sync(0xffffffffu, rs0, 1);
    rs0 += __shfl_xor_sync(0xffffffffu, rs0, 2);
    rs1 += __shfl_xor_sync(0xffffffffu, rs1, 1);
    rs1 += __shfl_xor_sync(0xffffffffu, rs1, 2);

    __syncthreads();
    float* Ored = (float*)smc;
    float* rsS  = (float*)(smc + 8192);
    if (kh == 1) {
        #pragma unroll
        for (int v = 0; v < 4; v++) {
            int cc = v*8 + g*2;
            Ored[(mi*16 + r)*32 + cc]       = oc[v][0];
            Ored[(mi*16 + r)*32 + cc + 1]   = oc[v][1];
            Ored[(mi*16 + r + 8)*32 + cc]   = oc[v][2];
            Ored[(mi*16 + r + 8)*32 + cc+1] = oc[v][3];
        }
        if (g == 0) { rsS[mi*16 + r] = rs0; rsS[mi*16 + r + 8] = rs1; }
    }
    __syncthreads();
    if (kh == 0) {
        float rt0 = 1.f / (rs0 + rsS[mi*16 + r]);
        float rt1 = 1.f / (rs1 + rsS[mi*16 + r + 8]);
        __half* o0 = Og + ((size_t)(b*SEQ + q0 + mi*16 + r))*DMODEL + h*DHEAD;
        __half* o1 = o0 + (size_t)8*DMODEL;
        #pragma unroll
        for (int v = 0; v < 4; v++) {
            int cc = v*8 + g*2;
            float p00 = (oc[v][0] + Ored[(mi*16 + r)*32 + cc])     * rt0;
            float p01 = (oc[v][1] + Ored[(mi*16 + r)*32 + cc + 1]) * rt0;
            float p10 = (oc[v][2] + Ored[(mi*16 + r + 8)*32 + cc])     * rt1;
            float p11 = (oc[v][3] + Ored[(mi*16 + r + 8)*32 + cc + 1]) * rt1;
            *(__half2*)(o0 + cc) = __floats2half2_rn(p00, p01);
            *(__half2*)(o1 + cc) = __floats2half2_rn(p10, p11);
        }
    }
}

// ---------------- orchestration ----------------
extern "C" void kernel_launch(void* const* d_in, const int* in_sizes, int n_in,
                              void* d_out, int out_size) {
    const float* enc      = (const float*)d_in[0];
    const float* dec      = (const float*)d_in[1];
    const int*   enc_mask = (const int*)  d_in[2];
    const int*   dec_mask = (const int*)  d_in[3];
    const float* W_tgt    = (const float*)d_in[4];
    const float* b_tgt    = (const float*)d_in[5];
    const float* sa_Wq = (const float*)d_in[6];  const float* sa_bq = (const float*)d_in[7];
    const float* sa_Wk = (const float*)d_in[8];  const float* sa_bk = (const float*)d_in[9];
    const float* sa_Wv = (const float*)d_in[10]; const float* sa_bv = (const float*)d_in[11];
    const float* sa_Wo = (const float*)d_in[12]; const float* sa_bo = (const float*)d_in[13];
    const float* sa_g  = (const float*)d_in[14]; const float* sa_b  = (const float*)d_in[15];
    const float* ca_Wq = (const float*)d_in[16]; const float* ca_bq = (const float*)d_in[17];
    const float* ca_Wk = (const float*)d_in[18]; const float* ca_bk = (const float*)d_in[19];
    const float* ca_Wv = (const float*)d_in[20]; const float* ca_bv = (const float*)d_in[21];
    const float* ca_Wo = (const float*)d_in[22]; const float* ca_bo = (const float*)d_in[23];
    const float* ca_g  = (const float*)d_in[24]; const float* ca_b  = (const float*)d_in[25];
    const float* ff_W1 = (const float*)d_in[26]; const float* ff_b1 = (const float*)d_in[27];
    const float* ff_W2 = (const float*)d_in[28]; const float* ff_b2 = (const float*)d_in[29];
    const float* ff_g  = (const float*)d_in[30]; const float* ff_b  = (const float*)d_in[31];

    float* fs = nullptr;
    __half* hs = nullptr;
    cudaGetSymbolAddress((void**)&fs, g_fscratch);
    cudaGetSymbolAddress((void**)&hs, g_hscratch);
    float* X = fs + OFF_X;
    float* T = fs + OFF_T;
    __half* Xh  = hs + HOFF_XH;
    __half* ENCh= hs + HOFF_ENC;
    __half* Qh  = hs + HOFF_Q;
    __half* Kh  = hs + HOFF_K;
    __half* Vh  = hs + HOFF_V;
    __half* Ch  = hs + HOFF_C;
    __half* Hh  = hs + HOFF_H;
    __half* Wh  = hs + HOFF_W;

    __half* hsaWq = Wh + 0*WSEG;
    __half* hsaWk = Wh + 1*WSEG;
    __half* hsaWv = Wh + 2*WSEG;
    __half* hsaWo = Wh + 3*WSEG;
    __half* hcaWq = Wh + 4*WSEG;
    __half* hcaWk = Wh + 5*WSEG;
    __half* hcaWv = Wh + 6*WSEG;
    __half* hcaWo = Wh + 7*WSEG;
    __half* hffW1 = Wh + 8*WSEG;
    __half* hffW2 = hffW1 + NLAYER*DMODEL*DFF;

    cudaFuncSetAttribute(attn_kernel, cudaFuncAttributeMaxDynamicSharedMemorySize, ATTN_SMEM);
    cudaFuncSetAttribute(gemm_kernel<false,false,true >, cudaFuncAttributeMaxDynamicSharedMemorySize, GEMM_SMEM);
    cudaFuncSetAttribute(gemm_kernel<false,true ,false>, cudaFuncAttributeMaxDynamicSharedMemorySize, GEMM_SMEM);
    cudaFuncSetAttribute(gemm_kernel<true ,false,true >, cudaFuncAttributeMaxDynamicSharedMemorySize, GEMM_SMEM);

    // ---- single batched conversion launch ----
    {
        CvtAll ca;
        const float* srcs[11] = {sa_Wq, sa_Wk, sa_Wv, sa_Wo, ca_Wq, ca_Wk, ca_Wv, ca_Wo,
                                 ff_W1, ff_W2, enc};
        __half* dsts[11] = {hsaWq, hsaWk, hsaWv, hsaWo, hcaWq, hcaWk, hcaWv, hcaWo,
                            hffW1, hffW2, ENCh};
        int nF = NLAYER*DMODEL*DFF;
        int szs[11] = {WSEG,WSEG,WSEG,WSEG,WSEG,WSEG,WSEG,WSEG, nF, nF, TD};
        long total = 0;
        for (int i = 0; i < 11; i++) { ca.src[i]=srcs[i]; ca.dst[i]=dsts[i]; ca.size[i]=szs[i]; total += szs[i]; }
        int nThreads = (int)(total/4);
        cvt_all_kernel<<<(nThreads + 255)/256, 256>>>(ca);
    }

    dim3 blkG(256), blkA(256), blkR(256);
    dim3 g_rows(TOK);
    dim3 g_qkv(6, 64);         // 3 sel x (256/128)
    dim3 g_256(2, 64);         // 256/128
    dim3 g_1024(8, 64);        // 1024/128
    dim3 g_attn(SEQ/64, NHEAD, BATCH);

    embed_kernel<<<g_rows, blkR>>>(dec, W_tgt, b_tgt, X, Xh);

    const int WD  = DMODEL*DMODEL;
    const int W1S = DMODEL*DFF;
    const int W2S = DFF*DMODEL;

    for (int i = 0; i < NLAYER; i++) {
        // ---- self attention ----
        {
            GArgs ga;
            ga.A[0]=Xh; ga.A[1]=Xh; ga.A[2]=Xh;
            ga.W[0]=hsaWq+i*WD; ga.W[1]=hsaWk+i*WD; ga.W[2]=hsaWv+i*WD;
            ga.bi[0]=sa_bq+i*DMODEL; ga.bi[1]=sa_bk+i*DMODEL; ga.bi[2]=sa_bv+i*DMODEL;
            ga.O[0]=Qh; ga.O[1]=Kh; ga.O[2]=Vh;
            gemm_kernel<false,false,true><<<g_qkv, blkG, GEMM_SMEM>>>(ga, nullptr, DMODEL, DMODEL, 1);
        }
        attn_kernel<<<g_attn, blkA, ATTN_SMEM>>>(Qh, Kh, Vh, Ch, dec_mask, SEQ, 1);
        {
            GArgs ga{};
            ga.A[0]=Ch; ga.W[0]=hsaWo+i*WD; ga.bi[0]=sa_bo+i*DMODEL; ga.O[0]=T;
            gemm_kernel<false,true,false><<<g_256, blkG, GEMM_SMEM>>>(ga, X, DMODEL, DMODEL, 1);
        }
        ln_kernel<<<g_rows, blkR>>>(T, sa_g+i*DMODEL, sa_b+i*DMODEL, X, Xh, 0);

        // ---- cross attention ----
        {
            GArgs ga;
            ga.A[0]=Xh; ga.A[1]=ENCh; ga.A[2]=ENCh;
            ga.W[0]=hcaWq+i*WD; ga.W[1]=hcaWk+i*WD; ga.W[2]=hcaWv+i*WD;
            ga.bi[0]=ca_bq+i*DMODEL; ga.bi[1]=ca_bk+i*DMODEL; ga.bi[2]=ca_bv+i*DMODEL;
            ga.O[0]=Qh; ga.O[1]=Kh; ga.O[2]=Vh;
            gemm_kernel<false,false,true><<<g_qkv, blkG, GEMM_SMEM>>>(ga, nullptr, DMODEL, DMODEL, 1);
        }
        attn_kernel<<<g_attn, blkA, ATTN_SMEM>>>(Qh, Kh, Vh, Ch, enc_mask, SEQ, 0);
        {
            GArgs ga{};
            ga.A[0]=Ch; ga.W[0]=hcaWo+i*WD; ga.bi[0]=ca_bo+i*DMODEL; ga.O[0]=T;
            gemm_kernel<false,true,false><<<g_256, blkG, GEMM_SMEM>>>(ga, X, DMODEL, DMODEL, 1);
        }
        ln_kernel<<<g_rows, blkR>>>(T, ca_g+i*DMODEL, ca_b+i*DMODEL, X, Xh, 0);

        // ---- FFN ----
        {
            GArgs ga{};
            ga.A[0]=Xh; ga.W[0]=hffW1+i*W1S; ga.bi[0]=ff_b1+i*DFF; ga.O[0]=Hh;
            gemm_kernel<true,false,true><<<g_1024, blkG, GEMM_SMEM>>>(ga, nullptr, DMODEL, DFF, 3);
        }
        {
            GArgs ga{};
            ga.A[0]=Hh; ga.W[0]=hffW2+i*W2S; ga.bi[0]=ff_b2+i*DMODEL; ga.O[0]=T;
            gemm_kernel<false,true,false><<<g_256, blkG, GEMM_SMEM>>>(ga, X, DFF, DMODEL, 1);
        }
        ln_kernel<<<g_rows, blkR>>>(T, ff_g+i*DMODEL, ff_b+i*DMODEL, X, Xh, (i < NLAYER-1) ? 1 : 0);
    }

    cudaMemcpyAsync(d_out, X, (size_t)TD*sizeof(float),
                    cudaMemcpyDeviceToDevice);
}